// round 11
// baseline (speedup 1.0000x reference)
#include <cuda_runtime.h>
#include <cuda_fp16.h>
#include <cstdint>
#include <math.h>

#define BDIM 4
#define TDIM 2048
#define CDIM 4096
#define FDIM 14336
#define MDIM (BDIM * TDIM)   // 8192

// ---------------- scratch (device globals; allocation-free rule) -----------
__device__ __half g_xk [(size_t)MDIM * CDIM];
__device__ __half g_xr [(size_t)MDIM * CDIM];
__device__ __half g_s  [(size_t)MDIM * FDIM];
__device__ __half g_kw [(size_t)FDIM * CDIM];
__device__ __half g_rw [(size_t)CDIM * CDIM];
__device__ __half g_vw [(size_t)CDIM * FDIM];
__device__ float  g_r  [(size_t)MDIM * CDIM];

// ---------------- helpers ----------------------------------------------------
__device__ __forceinline__ uint32_t smem_u32(const void* p) {
    uint32_t a;
    asm("{ .reg .u64 t; cvta.to.shared.u64 t, %1; cvt.u32.u64 %0, t; }" : "=r"(a) : "l"(p));
    return a;
}
__device__ __forceinline__ void cpa16(uint32_t dst, const void* src) {
    asm volatile("cp.async.cg.shared.global [%0], [%1], 16;" :: "r"(dst), "l"(src));
}
__device__ __forceinline__ void ldsm4(uint32_t& r0, uint32_t& r1, uint32_t& r2, uint32_t& r3,
                                      uint32_t addr) {
    asm volatile("ldmatrix.sync.aligned.m8n8.x4.shared.b16 {%0,%1,%2,%3}, [%4];"
                 : "=r"(r0), "=r"(r1), "=r"(r2), "=r"(r3) : "r"(addr));
}
__device__ __forceinline__ void mma_f16(float* c, const uint32_t* a, const uint32_t* b) {
    asm volatile(
        "mma.sync.aligned.m16n8k16.row.col.f32.f16.f16.f32 "
        "{%0,%1,%2,%3}, {%4,%5,%6,%7}, {%8,%9}, {%0,%1,%2,%3};"
        : "+f"(c[0]), "+f"(c[1]), "+f"(c[2]), "+f"(c[3])
        : "r"(a[0]), "r"(a[1]), "r"(a[2]), "r"(a[3]), "r"(b[0]), "r"(b[1]));
}
__device__ __forceinline__ uint32_t ph2(__half a, __half b) {
    __half2 t = __halves2half2(a, b);
    return *reinterpret_cast<uint32_t*>(&t);
}

// 64B-row XOR swizzle: 16B chunk c at row r stored at chunk (c ^ ((r>>1)&3))
__device__ __forceinline__ uint32_t swoff(int r, int c) {
    return (uint32_t)(r * 64 + ((c ^ ((r >> 1) & 3)) << 4));
}

// ---------------- elementwise kernels ---------------------------------------
__global__ void mix_kernel(const float4* __restrict__ x,
                           const float4* __restrict__ ls,
                           const float4* __restrict__ mk,
                           const float4* __restrict__ mr,
                           uint2* __restrict__ xk, uint2* __restrict__ xr) {
    const int C4 = CDIM / 4;
    int idx = blockIdx.x * blockDim.x + threadIdx.x;
    int c4 = idx % C4;
    int bt = idx / C4;
    int t  = bt % TDIM;
    int b  = bt / TDIM;

    float4 xv = x[idx];
    float4 pv = (t == 0) ? ls[b * C4 + c4] : x[idx - C4];
    float4 k4 = mk[c4];
    float4 r4 = mr[c4];

    float kk[4], rr[4];
    kk[0] = fmaf(pv.x - xv.x, k4.x, xv.x);
    kk[1] = fmaf(pv.y - xv.y, k4.y, xv.y);
    kk[2] = fmaf(pv.z - xv.z, k4.z, xv.z);
    kk[3] = fmaf(pv.w - xv.w, k4.w, xv.w);
    rr[0] = fmaf(pv.x - xv.x, r4.x, xv.x);
    rr[1] = fmaf(pv.y - xv.y, r4.y, xv.y);
    rr[2] = fmaf(pv.z - xv.z, r4.z, xv.z);
    rr[3] = fmaf(pv.w - xv.w, r4.w, xv.w);

    xk[idx] = make_uint2(ph2(__float2half_rn(kk[0]), __float2half_rn(kk[1])),
                         ph2(__float2half_rn(kk[2]), __float2half_rn(kk[3])));
    xr[idx] = make_uint2(ph2(__float2half_rn(rr[0]), __float2half_rn(rr[1])),
                         ph2(__float2half_rn(rr[2]), __float2half_rn(rr[3])));
}

__global__ void cvt_kernel(const float4* __restrict__ in,
                           uint4* __restrict__ oh, size_t n8) {
    size_t i = (size_t)blockIdx.x * blockDim.x + threadIdx.x;
    if (i >= n8) return;
    float4 a = in[2 * i], b = in[2 * i + 1];
    oh[i] = make_uint4(ph2(__float2half_rn(a.x), __float2half_rn(a.y)),
                       ph2(__float2half_rn(a.z), __float2half_rn(a.w)),
                       ph2(__float2half_rn(b.x), __float2half_rn(b.y)),
                       ph2(__float2half_rn(b.z), __float2half_rn(b.w)));
}

__global__ void state_kernel(const float* __restrict__ x, float* __restrict__ outs) {
    int idx = blockIdx.x * blockDim.x + threadIdx.x;
    int b = idx / CDIM;
    int c = idx % CDIM;
    outs[idx] = x[((size_t)b * TDIM + (TDIM - 1)) * CDIM + c];
}

// ---------------- fp16 HMMA GEMM (all three GEMMs) ---------------------------
// C[M,N] = A[M,K] * B[N,K]^T, fp16 inputs, fp32 accum.
// CTA 128x256, 16 warps (512 thr), warp 64x32, 6 stages of BK=32,
// TWO stages consumed per barrier (effective BK=64 per sync).
// XOR-swizzled 64B rows. epi 0: relu^2->fp16 | 1: sigmoid->fp32 | 2: *Rm->fp32
#define ASEC   (128 * 64)            // 8192
#define BSEC   (256 * 64)            // 16384
#define STAGE1 (ASEC + BSEC)         // 24576
#define NST1   6
#define SMEM1  (NST1 * STAGE1)       // 147456

__global__ void __launch_bounds__(512, 1)
gemm_f16(const __half* __restrict__ A, const __half* __restrict__ B,
         int N, int K, int Ntiles, int epi,
         float* __restrict__ Cf, __half* __restrict__ Chf,
         const float* __restrict__ Rm) {
    extern __shared__ char smem[];
    const uint32_t sb = smem_u32(smem);
    const int tid  = threadIdx.x;
    const int wid  = tid >> 5;
    const int lane = tid & 31;
    const int wm   = wid & 1;        // 2 warp-rows (64 each)
    const int wn   = wid >> 1;       // 8 warp-cols (32 each)

    // band-swizzled tile mapping (bands of 16 M-tiles)
    int bid = blockIdx.x;
    int bandCtas = 16 * Ntiles;
    int band = bid / bandCtas, rmd = bid % bandCtas;
    int nt = rmd >> 4;
    int mt = band * 16 + (rmd & 15);
    const size_t m0 = (size_t)mt * 128;
    const size_t n0 = (size_t)nt * 256;

    const size_t K2 = (size_t)K * 2;
    const char* pA = (const char*)(A + m0 * (size_t)K);
    const char* pB = (const char*)(B + n0 * (size_t)K);

    const int nk = K >> 5;   // BK=32 stages along K (always even here)

    const int cr = tid >> 2;
    const int cc = tid & 3;
    const uint32_t aoff  = swoff(cr, cc);
    const uint32_t boff0 = swoff(cr, cc);
    const uint32_t boff1 = swoff(cr + 128, cc);

    // prologue: stages 0..3, one commit each
#pragma unroll
    for (int s = 0; s < 4; ++s) {
        const uint32_t base = sb + s * STAGE1;
        const size_t kb = (size_t)s * 64;
        size_t g  = (size_t)cr * K2 + kb + (size_t)cc * 16;
        size_t g1 = (size_t)(cr + 128) * K2 + kb + (size_t)cc * 16;
        cpa16(base + aoff, pA + g);
        cpa16(base + ASEC + boff0, pB + g);
        cpa16(base + ASEC + boff1, pB + g1);
        asm volatile("cp.async.commit_group;" ::: "memory");
    }

    float acc[4][4][4];
#pragma unroll
    for (int i = 0; i < 4; ++i)
#pragma unroll
        for (int j = 0; j < 4; ++j)
#pragma unroll
            for (int q = 0; q < 4; ++q) acc[i][j][q] = 0.0f;

    const int rl_a   = (lane & 7) + ((lane >> 3) & 1) * 8;
    const int sel_a  = (rl_a >> 1) & 3;
    const int cb_a   = lane >> 4;
    const uint32_t arow  = (uint32_t)(rl_a * 64);
    const uint32_t acol0 = (uint32_t)(((0 + cb_a) ^ sel_a) << 4);
    const uint32_t acol1 = (uint32_t)(((2 + cb_a) ^ sel_a) << 4);

    const int rl_b   = (lane & 7) + (lane >> 4) * 8;
    const int sel_b  = (rl_b >> 1) & 3;
    const int cb_b   = (lane >> 3) & 1;
    const uint32_t brow  = (uint32_t)(rl_b * 64);
    const uint32_t bcol0 = (uint32_t)(((0 + cb_b) ^ sel_b) << 4);
    const uint32_t bcol1 = (uint32_t)(((2 + cb_b) ^ sel_b) << 4);

    // stage counters (mod 6): compute pair {sc0, sc1}, prefetch pair {sp0, sp1}
    int sc0 = 0, sc1 = 1, sp0 = 4, sp1 = 5;
    const int half = nk >> 1;
    for (int j = 0; j < half; ++j) {
        // stages 2j and 2j+1 complete when <=2 groups outstanding
        asm volatile("cp.async.wait_group 2;" ::: "memory");
        __syncthreads();

        // prefetch stages 2j+4, 2j+5 (commits unconditional to keep counts aligned)
        {
            int ks = 2 * j + 4;
            if (ks < nk) {
                const uint32_t base = sb + sp0 * STAGE1;
                const size_t kb = (size_t)ks * 64;
                size_t g  = (size_t)cr * K2 + kb + (size_t)cc * 16;
                size_t g1 = (size_t)(cr + 128) * K2 + kb + (size_t)cc * 16;
                cpa16(base + aoff, pA + g);
                cpa16(base + ASEC + boff0, pB + g);
                cpa16(base + ASEC + boff1, pB + g1);
            }
            asm volatile("cp.async.commit_group;" ::: "memory");
            if (ks + 1 < nk) {
                const uint32_t base = sb + sp1 * STAGE1;
                const size_t kb = (size_t)(ks + 1) * 64;
                size_t g  = (size_t)cr * K2 + kb + (size_t)cc * 16;
                size_t g1 = (size_t)(cr + 128) * K2 + kb + (size_t)cc * 16;
                cpa16(base + aoff, pA + g);
                cpa16(base + ASEC + boff0, pB + g);
                cpa16(base + ASEC + boff1, pB + g1);
            }
            asm volatile("cp.async.commit_group;" ::: "memory");
        }

        // compute both stages: 4 kk slices of BK=16 each
#pragma unroll
        for (int half_s = 0; half_s < 2; ++half_s) {
            const uint32_t sbase = sb + (half_s ? sc1 : sc0) * STAGE1;
            const uint32_t aS = sbase;
            const uint32_t bS = sbase + ASEC;
#pragma unroll
            for (int kk = 0; kk < 2; ++kk) {
                const uint32_t acol = kk ? acol1 : acol0;
                const uint32_t bcol = kk ? bcol1 : bcol0;
                uint32_t af[4][4], bf[4][2];
#pragma unroll
                for (int mi = 0; mi < 4; ++mi) {
                    uint32_t ra = (uint32_t)((wm * 64 + mi * 16) * 64) + arow + acol;
                    ldsm4(af[mi][0], af[mi][1], af[mi][2], af[mi][3], aS + ra);
                }
#pragma unroll
                for (int nj = 0; nj < 2; ++nj) {
                    uint32_t rb = (uint32_t)((wn * 32 + nj * 16) * 64) + brow + bcol;
                    uint32_t t0, t1, t2, t3;
                    ldsm4(t0, t1, t2, t3, bS + rb);
                    bf[nj * 2][0] = t0; bf[nj * 2][1] = t1;
                    bf[nj * 2 + 1][0] = t2; bf[nj * 2 + 1][1] = t3;
                }
#pragma unroll
                for (int mi = 0; mi < 4; ++mi)
#pragma unroll
                    for (int ni = 0; ni < 4; ++ni)
                        mma_f16(acc[mi][ni], af[mi], bf[ni]);
            }
        }

        sc0 += 2; if (sc0 >= NST1) sc0 -= NST1;
        sc1 += 2; if (sc1 >= NST1) sc1 -= NST1;
        sp0 += 2; if (sp0 >= NST1) sp0 -= NST1;
        sp1 += 2; if (sp1 >= NST1) sp1 -= NST1;
    }

    // ---- epilogue ----
    const size_t mw = m0 + wm * 64;
    const size_t nw = n0 + wn * 32;
    const int tr = lane >> 2;
    const int tc = (lane & 3) * 2;
#pragma unroll
    for (int mi = 0; mi < 4; ++mi)
#pragma unroll
        for (int nj = 0; nj < 4; ++nj) {
            const float* c = acc[mi][nj];
            const size_t row = mw + mi * 16 + tr;
            const size_t col = nw + nj * 8 + tc;
#pragma unroll
            for (int h = 0; h < 2; ++h) {
                const size_t base = (row + h * 8) * (size_t)N + col;
                float v0 = c[h * 2], v1 = c[h * 2 + 1];
                if (epi == 0) {                 // relu^2 -> fp16
                    v0 = fmaxf(v0, 0.0f); v0 *= v0;
                    v1 = fmaxf(v1, 0.0f); v1 *= v1;
                    *reinterpret_cast<uint32_t*>(Chf + base) =
                        ph2(__float2half_rn(v0), __float2half_rn(v1));
                } else if (epi == 1) {          // sigmoid -> fp32
                    float2 o;
                    o.x = 1.0f / (1.0f + expf(-v0));
                    o.y = 1.0f / (1.0f + expf(-v1));
                    *reinterpret_cast<float2*>(Cf + base) = o;
                } else {                        // * r -> fp32
                    float2 rv = *reinterpret_cast<const float2*>(Rm + base);
                    float2 o;
                    o.x = v0 * rv.x;
                    o.y = v1 * rv.y;
                    *reinterpret_cast<float2*>(Cf + base) = o;
                }
            }
        }
}

// ---------------- launch -----------------------------------------------------
extern "C" void kernel_launch(void* const* d_in, const int* in_sizes, int n_in,
                              void* d_out, int out_size) {
    const float* x  = (const float*)d_in[0];
    const float* ls = (const float*)d_in[1];
    const float* mk = (const float*)d_in[2];
    const float* mr = (const float*)d_in[3];
    const float* kw = (const float*)d_in[4];   // (F, C)
    const float* rw = (const float*)d_in[5];   // (C, C)
    const float* vw = (const float*)d_in[6];   // (C, F)
    float* out = (float*)d_out;

    __half *xk, *xr, *s, *kwp, *rwp, *vwp;
    float* r;
    cudaGetSymbolAddress((void**)&xk,  g_xk);
    cudaGetSymbolAddress((void**)&xr,  g_xr);
    cudaGetSymbolAddress((void**)&s,   g_s);
    cudaGetSymbolAddress((void**)&kwp, g_kw);
    cudaGetSymbolAddress((void**)&rwp, g_rw);
    cudaGetSymbolAddress((void**)&vwp, g_vw);
    cudaGetSymbolAddress((void**)&r,   g_r);

    cudaFuncSetAttribute(gemm_f16, cudaFuncAttributeMaxDynamicSharedMemorySize, SMEM1);

    // 1) token-shift mix -> fp16 xk, xr
    mix_kernel<<<(MDIM * (CDIM / 4)) / 256, 256>>>(
        (const float4*)x, (const float4*)ls, (const float4*)mk, (const float4*)mr,
        (uint2*)xk, (uint2*)xr);

    // 2) weight prep: all single fp16
    {
        size_t n8;
        n8 = (size_t)FDIM * CDIM / 8;
        cvt_kernel<<<(unsigned)((n8 + 255) / 256), 256>>>((const float4*)kw, (uint4*)kwp, n8);
        n8 = (size_t)CDIM * CDIM / 8;
        cvt_kernel<<<(unsigned)((n8 + 255) / 256), 256>>>((const float4*)rw, (uint4*)rwp, n8);
        n8 = (size_t)CDIM * FDIM / 8;
        cvt_kernel<<<(unsigned)((n8 + 255) / 256), 256>>>((const float4*)vw, (uint4*)vwp, n8);
    }

    // 3) S = relu(xk @ Kw^T)^2 -> fp16           [M=8192, N=14336, K=4096]
    gemm_f16<<<(MDIM / 128) * (FDIM / 256), 512, SMEM1>>>(
        xk, kwp, FDIM, CDIM, FDIM / 256, 0, nullptr, s, nullptr);

    // 4) R = sigmoid(xr @ Rw^T) -> fp32          [M=8192, N=4096, K=4096]
    gemm_f16<<<(MDIM / 128) * (CDIM / 256), 512, SMEM1>>>(
        xr, rwp, CDIM, CDIM, CDIM / 256, 1, r, nullptr, nullptr);

    // 5) out = R * (S @ Vw^T)  -> fp32           [M=8192, N=4096, K=14336]
    gemm_f16<<<(MDIM / 128) * (CDIM / 256), 512, SMEM1>>>(
        s, vwp, CDIM, FDIM, CDIM / 256, 2, out, nullptr, r);

    // 6) new_state = x[:, -1, :]
    state_kernel<<<(BDIM * CDIM) / 256, 256>>>(x, out + (size_t)MDIM * CDIM);
}

// round 12
// speedup vs baseline: 1.0115x; 1.0115x over previous
#include <cuda_runtime.h>
#include <cuda_fp16.h>
#include <cstdint>
#include <math.h>

#define BDIM 4
#define TDIM 2048
#define CDIM 4096
#define FDIM 14336
#define MDIM (BDIM * TDIM)   // 8192

// ---------------- scratch (device globals; allocation-free rule) -----------
__device__ __half g_xk [(size_t)MDIM * CDIM];
__device__ __half g_xr [(size_t)MDIM * CDIM];
__device__ __half g_s  [(size_t)MDIM * FDIM];
__device__ __half g_kw [(size_t)FDIM * CDIM];
__device__ __half g_rw [(size_t)CDIM * CDIM];
__device__ __half g_vw [(size_t)CDIM * FDIM];
__device__ float  g_r  [(size_t)MDIM * CDIM];

// ---------------- helpers ----------------------------------------------------
__device__ __forceinline__ uint32_t smem_u32(const void* p) {
    uint32_t a;
    asm("{ .reg .u64 t; cvta.to.shared.u64 t, %1; cvt.u32.u64 %0, t; }" : "=r"(a) : "l"(p));
    return a;
}
__device__ __forceinline__ void cpa16(uint32_t dst, const void* src) {
    asm volatile("cp.async.cg.shared.global [%0], [%1], 16;" :: "r"(dst), "l"(src));
}
__device__ __forceinline__ void ldsm4(uint32_t& r0, uint32_t& r1, uint32_t& r2, uint32_t& r3,
                                      uint32_t addr) {
    asm volatile("ldmatrix.sync.aligned.m8n8.x4.shared.b16 {%0,%1,%2,%3}, [%4];"
                 : "=r"(r0), "=r"(r1), "=r"(r2), "=r"(r3) : "r"(addr));
}
__device__ __forceinline__ void mma_f16(float* c, const uint32_t* a, const uint32_t* b) {
    asm volatile(
        "mma.sync.aligned.m16n8k16.row.col.f32.f16.f16.f32 "
        "{%0,%1,%2,%3}, {%4,%5,%6,%7}, {%8,%9}, {%0,%1,%2,%3};"
        : "+f"(c[0]), "+f"(c[1]), "+f"(c[2]), "+f"(c[3])
        : "r"(a[0]), "r"(a[1]), "r"(a[2]), "r"(a[3]), "r"(b[0]), "r"(b[1]));
}
__device__ __forceinline__ uint32_t ph2(__half a, __half b) {
    __half2 t = __halves2half2(a, b);
    return *reinterpret_cast<uint32_t*>(&t);
}

// 64B-row XOR swizzle: 16B chunk c at row r stored at chunk (c ^ ((r>>1)&3))
__device__ __forceinline__ uint32_t swoff(int r, int c) {
    return (uint32_t)(r * 64 + ((c ^ ((r >> 1) & 3)) << 4));
}

// ---------------- elementwise kernels ---------------------------------------
__global__ void mix_kernel(const float4* __restrict__ x,
                           const float4* __restrict__ ls,
                           const float4* __restrict__ mk,
                           const float4* __restrict__ mr,
                           uint2* __restrict__ xk, uint2* __restrict__ xr) {
    const int C4 = CDIM / 4;
    int idx = blockIdx.x * blockDim.x + threadIdx.x;
    int c4 = idx % C4;
    int bt = idx / C4;
    int t  = bt % TDIM;
    int b  = bt / TDIM;

    float4 xv = x[idx];
    float4 pv = (t == 0) ? ls[b * C4 + c4] : x[idx - C4];
    float4 k4 = mk[c4];
    float4 r4 = mr[c4];

    float kk[4], rr[4];
    kk[0] = fmaf(pv.x - xv.x, k4.x, xv.x);
    kk[1] = fmaf(pv.y - xv.y, k4.y, xv.y);
    kk[2] = fmaf(pv.z - xv.z, k4.z, xv.z);
    kk[3] = fmaf(pv.w - xv.w, k4.w, xv.w);
    rr[0] = fmaf(pv.x - xv.x, r4.x, xv.x);
    rr[1] = fmaf(pv.y - xv.y, r4.y, xv.y);
    rr[2] = fmaf(pv.z - xv.z, r4.z, xv.z);
    rr[3] = fmaf(pv.w - xv.w, r4.w, xv.w);

    xk[idx] = make_uint2(ph2(__float2half_rn(kk[0]), __float2half_rn(kk[1])),
                         ph2(__float2half_rn(kk[2]), __float2half_rn(kk[3])));
    xr[idx] = make_uint2(ph2(__float2half_rn(rr[0]), __float2half_rn(rr[1])),
                         ph2(__float2half_rn(rr[2]), __float2half_rn(rr[3])));
}

__global__ void cvt_kernel(const float4* __restrict__ in,
                           uint4* __restrict__ oh, size_t n8) {
    size_t i = (size_t)blockIdx.x * blockDim.x + threadIdx.x;
    if (i >= n8) return;
    float4 a = in[2 * i], b = in[2 * i + 1];
    oh[i] = make_uint4(ph2(__float2half_rn(a.x), __float2half_rn(a.y)),
                       ph2(__float2half_rn(a.z), __float2half_rn(a.w)),
                       ph2(__float2half_rn(b.x), __float2half_rn(b.y)),
                       ph2(__float2half_rn(b.z), __float2half_rn(b.w)));
}

__global__ void state_kernel(const float* __restrict__ x, float* __restrict__ outs) {
    int idx = blockIdx.x * blockDim.x + threadIdx.x;
    int b = idx / CDIM;
    int c = idx % CDIM;
    outs[idx] = x[((size_t)b * TDIM + (TDIM - 1)) * CDIM + c];
}

// ---------------- fp16 HMMA GEMM body (R10 structure) -------------------------
// C[M,N] = A[M,K] * B[N,K]^T, fp16 in, fp32 accum. CTA 128x256, 16 warps,
// warp 64x32, BK=32, 6-stage cp.async (wait_group 4), XOR-swizzled 64B rows.
#define ASEC   (128 * 64)            // 8192
#define BSEC   (256 * 64)            // 16384
#define STAGE1 (ASEC + BSEC)         // 24576
#define NST1   6
#define SMEM1  (NST1 * STAGE1)       // 147456

__device__ __forceinline__ void gemm_body(
        uint32_t sb,
        const __half* __restrict__ A, const __half* __restrict__ B,
        int bid, int N, int K, int Ntiles, int epi,
        float* __restrict__ Cf, __half* __restrict__ Chf,
        const float* __restrict__ Rm) {
    const int tid  = threadIdx.x;
    const int wid  = tid >> 5;
    const int lane = tid & 31;
    const int wm   = wid & 1;        // 2 warp-rows (64 each)
    const int wn   = wid >> 1;       // 8 warp-cols (32 each)

    // band-swizzled tile mapping (bands of 16 M-tiles)
    int bandCtas = 16 * Ntiles;
    int band = bid / bandCtas, rmd = bid % bandCtas;
    int nt = rmd >> 4;
    int mt = band * 16 + (rmd & 15);
    const size_t m0 = (size_t)mt * 128;
    const size_t n0 = (size_t)nt * 256;

    const size_t K2 = (size_t)K * 2;
    const char* pA = (const char*)(A + m0 * (size_t)K);
    const char* pB = (const char*)(B + n0 * (size_t)K);

    const int nk = K >> 5;   // BK = 32

    const int cr = tid >> 2;
    const int cc = tid & 3;
    const uint32_t aoff  = swoff(cr, cc);
    const uint32_t boff0 = swoff(cr, cc);
    const uint32_t boff1 = swoff(cr + 128, cc);

#pragma unroll
    for (int s = 0; s < 5; ++s) {
        const uint32_t base = sb + s * STAGE1;
        const size_t kb = (size_t)s * 64;
        size_t g  = (size_t)cr * K2 + kb + (size_t)cc * 16;
        size_t g1 = (size_t)(cr + 128) * K2 + kb + (size_t)cc * 16;
        cpa16(base + aoff, pA + g);
        cpa16(base + ASEC + boff0, pB + g);
        cpa16(base + ASEC + boff1, pB + g1);
        asm volatile("cp.async.commit_group;" ::: "memory");
    }

    float acc[4][4][4];
#pragma unroll
    for (int i = 0; i < 4; ++i)
#pragma unroll
        for (int j = 0; j < 4; ++j)
#pragma unroll
            for (int q = 0; q < 4; ++q) acc[i][j][q] = 0.0f;

    const int rl_a   = (lane & 7) + ((lane >> 3) & 1) * 8;
    const int sel_a  = (rl_a >> 1) & 3;
    const int cb_a   = lane >> 4;
    const uint32_t arow  = (uint32_t)(rl_a * 64);
    const uint32_t acol0 = (uint32_t)(((0 + cb_a) ^ sel_a) << 4);
    const uint32_t acol1 = (uint32_t)(((2 + cb_a) ^ sel_a) << 4);

    const int rl_b   = (lane & 7) + (lane >> 4) * 8;
    const int sel_b  = (rl_b >> 1) & 3;
    const int cb_b   = (lane >> 3) & 1;
    const uint32_t brow  = (uint32_t)(rl_b * 64);
    const uint32_t bcol0 = (uint32_t)(((0 + cb_b) ^ sel_b) << 4);
    const uint32_t bcol1 = (uint32_t)(((2 + cb_b) ^ sel_b) << 4);

    int stC = 0, stP = 5;
    for (int kt = 0; kt < nk; ++kt) {
        asm volatile("cp.async.wait_group 4;" ::: "memory");
        __syncthreads();

        if (kt + 5 < nk) {
            const uint32_t base = sb + stP * STAGE1;
            const size_t kb = (size_t)(kt + 5) * 64;
            size_t g  = (size_t)cr * K2 + kb + (size_t)cc * 16;
            size_t g1 = (size_t)(cr + 128) * K2 + kb + (size_t)cc * 16;
            cpa16(base + aoff, pA + g);
            cpa16(base + ASEC + boff0, pB + g);
            cpa16(base + ASEC + boff1, pB + g1);
        }
        asm volatile("cp.async.commit_group;" ::: "memory");

        const uint32_t sbase = sb + stC * STAGE1;
        const uint32_t aS = sbase;
        const uint32_t bS = sbase + ASEC;

#pragma unroll
        for (int kk = 0; kk < 2; ++kk) {
            const uint32_t acol = kk ? acol1 : acol0;
            const uint32_t bcol = kk ? bcol1 : bcol0;
            uint32_t af[4][4], bf[4][2];
#pragma unroll
            for (int mi = 0; mi < 4; ++mi) {
                uint32_t ra = (uint32_t)((wm * 64 + mi * 16) * 64) + arow + acol;
                ldsm4(af[mi][0], af[mi][1], af[mi][2], af[mi][3], aS + ra);
            }
#pragma unroll
            for (int nj = 0; nj < 2; ++nj) {
                uint32_t rb = (uint32_t)((wn * 32 + nj * 16) * 64) + brow + bcol;
                uint32_t t0, t1, t2, t3;
                ldsm4(t0, t1, t2, t3, bS + rb);
                bf[nj * 2][0] = t0; bf[nj * 2][1] = t1;
                bf[nj * 2 + 1][0] = t2; bf[nj * 2 + 1][1] = t3;
            }
#pragma unroll
            for (int mi = 0; mi < 4; ++mi)
#pragma unroll
                for (int ni = 0; ni < 4; ++ni)
                    mma_f16(acc[mi][ni], af[mi], bf[ni]);
        }

        if (++stC == NST1) stC = 0;
        if (++stP == NST1) stP = 0;
    }

    // ---- epilogue ----
    const size_t mw = m0 + wm * 64;
    const size_t nw = n0 + wn * 32;
    const int tr = lane >> 2;
    const int tc = (lane & 3) * 2;
#pragma unroll
    for (int mi = 0; mi < 4; ++mi)
#pragma unroll
        for (int nj = 0; nj < 4; ++nj) {
            const float* c = acc[mi][nj];
            const size_t row = mw + mi * 16 + tr;
            const size_t col = nw + nj * 8 + tc;
#pragma unroll
            for (int h = 0; h < 2; ++h) {
                const size_t base = (row + h * 8) * (size_t)N + col;
                float v0 = c[h * 2], v1 = c[h * 2 + 1];
                if (epi == 0) {                 // relu^2 -> fp16
                    v0 = fmaxf(v0, 0.0f); v0 *= v0;
                    v1 = fmaxf(v1, 0.0f); v1 *= v1;
                    *reinterpret_cast<uint32_t*>(Chf + base) =
                        ph2(__float2half_rn(v0), __float2half_rn(v1));
                } else if (epi == 1) {          // sigmoid -> fp32
                    float2 o;
                    o.x = 1.0f / (1.0f + expf(-v0));
                    o.y = 1.0f / (1.0f + expf(-v1));
                    *reinterpret_cast<float2*>(Cf + base) = o;
                } else {                        // * r -> fp32
                    float2 rv = *reinterpret_cast<const float2*>(Rm + base);
                    float2 o;
                    o.x = v0 * rv.x;
                    o.y = v1 * rv.y;
                    *reinterpret_cast<float2*>(Cf + base) = o;
                }
            }
        }
}

// GEMM1 (S) and GEMM2 (R) fused: independent inputs, one launch.
#define G1_CTAS ((MDIM / 128) * (FDIM / 256))   // 3584
#define G2_CTAS ((MDIM / 128) * (CDIM / 256))   // 1024

__global__ void __launch_bounds__(512, 1)
gemm_fused12(const __half* __restrict__ xk, const __half* __restrict__ kw,
             __half* __restrict__ s,
             const __half* __restrict__ xr, const __half* __restrict__ rw,
             float* __restrict__ r) {
    extern __shared__ char smem[];
    const uint32_t sb = smem_u32(smem);
    int bid = blockIdx.x;
    if (bid < G1_CTAS) {
        gemm_body(sb, xk, kw, bid, FDIM, CDIM, FDIM / 256, 0, nullptr, s, nullptr);
    } else {
        gemm_body(sb, xr, rw, bid - G1_CTAS, CDIM, CDIM, CDIM / 256, 1, r, nullptr, nullptr);
    }
}

__global__ void __launch_bounds__(512, 1)
gemm3(const __half* __restrict__ s, const __half* __restrict__ vw,
      float* __restrict__ out, const float* __restrict__ r) {
    extern __shared__ char smem[];
    const uint32_t sb = smem_u32(smem);
    gemm_body(sb, s, vw, blockIdx.x, CDIM, FDIM, CDIM / 256, 2, out, nullptr, r);
}

// ---------------- launch -----------------------------------------------------
extern "C" void kernel_launch(void* const* d_in, const int* in_sizes, int n_in,
                              void* d_out, int out_size) {
    const float* x  = (const float*)d_in[0];
    const float* ls = (const float*)d_in[1];
    const float* mk = (const float*)d_in[2];
    const float* mr = (const float*)d_in[3];
    const float* kw = (const float*)d_in[4];   // (F, C)
    const float* rw = (const float*)d_in[5];   // (C, C)
    const float* vw = (const float*)d_in[6];   // (C, F)
    float* out = (float*)d_out;

    __half *xk, *xr, *s, *kwp, *rwp, *vwp;
    float* r;
    cudaGetSymbolAddress((void**)&xk,  g_xk);
    cudaGetSymbolAddress((void**)&xr,  g_xr);
    cudaGetSymbolAddress((void**)&s,   g_s);
    cudaGetSymbolAddress((void**)&kwp, g_kw);
    cudaGetSymbolAddress((void**)&rwp, g_rw);
    cudaGetSymbolAddress((void**)&vwp, g_vw);
    cudaGetSymbolAddress((void**)&r,   g_r);

    cudaFuncSetAttribute(gemm_fused12, cudaFuncAttributeMaxDynamicSharedMemorySize, SMEM1);
    cudaFuncSetAttribute(gemm3,        cudaFuncAttributeMaxDynamicSharedMemorySize, SMEM1);

    // 1) token-shift mix -> fp16 xk, xr
    mix_kernel<<<(MDIM * (CDIM / 4)) / 256, 256>>>(
        (const float4*)x, (const float4*)ls, (const float4*)mk, (const float4*)mr,
        (uint2*)xk, (uint2*)xr);

    // 2) weight prep: all single fp16
    {
        size_t n8;
        n8 = (size_t)FDIM * CDIM / 8;
        cvt_kernel<<<(unsigned)((n8 + 255) / 256), 256>>>((const float4*)kw, (uint4*)kwp, n8);
        n8 = (size_t)CDIM * CDIM / 8;
        cvt_kernel<<<(unsigned)((n8 + 255) / 256), 256>>>((const float4*)rw, (uint4*)rwp, n8);
        n8 = (size_t)CDIM * FDIM / 8;
        cvt_kernel<<<(unsigned)((n8 + 255) / 256), 256>>>((const float4*)vw, (uint4*)vwp, n8);
    }

    // 3+4) fused: S = relu(xk @ Kw^T)^2 -> fp16  AND  R = sigmoid(xr @ Rw^T)
    gemm_fused12<<<G1_CTAS + G2_CTAS, 512, SMEM1>>>(xk, kwp, s, xr, rwp, r);

    // 5) out = R * (S @ Vw^T)  -> fp32           [M=8192, N=4096, K=14336]
    gemm3<<<G2_CTAS, 512, SMEM1>>>(s, vwp, out, r);

    // 6) new_state = x[:, -1, :]
    state_kernel<<<(BDIM * CDIM) / 256, 256>>>(x, out + (size_t)MDIM * CDIM);
}

// round 13
// speedup vs baseline: 1.0339x; 1.0221x over previous
#include <cuda_runtime.h>
#include <cuda_fp16.h>
#include <cstdint>
#include <math.h>

#define BDIM 4
#define TDIM 2048
#define CDIM 4096
#define FDIM 14336
#define MDIM (BDIM * TDIM)   // 8192

// ---------------- scratch (device globals; allocation-free rule) -----------
__device__ __half g_xk [(size_t)MDIM * CDIM];
__device__ __half g_xr [(size_t)MDIM * CDIM];
__device__ __half g_s  [(size_t)MDIM * FDIM];
__device__ __half g_kw [(size_t)FDIM * CDIM];
__device__ __half g_rw [(size_t)CDIM * CDIM];
__device__ __half g_vw [(size_t)CDIM * FDIM];
__device__ float  g_r  [(size_t)MDIM * CDIM];

// ---------------- helpers ----------------------------------------------------
__device__ __forceinline__ uint32_t smem_u32(const void* p) {
    uint32_t a;
    asm("{ .reg .u64 t; cvta.to.shared.u64 t, %1; cvt.u32.u64 %0, t; }" : "=r"(a) : "l"(p));
    return a;
}
__device__ __forceinline__ void cpa16(uint32_t dst, const void* src) {
    asm volatile("cp.async.cg.shared.global [%0], [%1], 16;" :: "r"(dst), "l"(src));
}
__device__ __forceinline__ void ldsm4(uint32_t& r0, uint32_t& r1, uint32_t& r2, uint32_t& r3,
                                      uint32_t addr) {
    asm volatile("ldmatrix.sync.aligned.m8n8.x4.shared.b16 {%0,%1,%2,%3}, [%4];"
                 : "=r"(r0), "=r"(r1), "=r"(r2), "=r"(r3) : "r"(addr));
}
__device__ __forceinline__ void mma_f16(float* c, const uint32_t* a, const uint32_t* b) {
    asm volatile(
        "mma.sync.aligned.m16n8k16.row.col.f32.f16.f16.f32 "
        "{%0,%1,%2,%3}, {%4,%5,%6,%7}, {%8,%9}, {%0,%1,%2,%3};"
        : "+f"(c[0]), "+f"(c[1]), "+f"(c[2]), "+f"(c[3])
        : "r"(a[0]), "r"(a[1]), "r"(a[2]), "r"(a[3]), "r"(b[0]), "r"(b[1]));
}
__device__ __forceinline__ uint32_t ph2(__half a, __half b) {
    __half2 t = __halves2half2(a, b);
    return *reinterpret_cast<uint32_t*>(&t);
}

// 64B-row XOR swizzle: 16B chunk c at row r stored at chunk (c ^ ((r>>1)&3))
__device__ __forceinline__ uint32_t swoff(int r, int c) {
    return (uint32_t)(r * 64 + ((c ^ ((r >> 1) & 3)) << 4));
}

// ---------------- elementwise kernels ---------------------------------------
__global__ void mix_kernel(const float4* __restrict__ x,
                           const float4* __restrict__ ls,
                           const float4* __restrict__ mk,
                           const float4* __restrict__ mr,
                           uint2* __restrict__ xk, uint2* __restrict__ xr) {
    const int C4 = CDIM / 4;
    int idx = blockIdx.x * blockDim.x + threadIdx.x;
    int c4 = idx % C4;
    int bt = idx / C4;
    int t  = bt % TDIM;
    int b  = bt / TDIM;

    float4 xv = x[idx];
    float4 pv = (t == 0) ? ls[b * C4 + c4] : x[idx - C4];
    float4 k4 = mk[c4];
    float4 r4 = mr[c4];

    float kk[4], rr[4];
    kk[0] = fmaf(pv.x - xv.x, k4.x, xv.x);
    kk[1] = fmaf(pv.y - xv.y, k4.y, xv.y);
    kk[2] = fmaf(pv.z - xv.z, k4.z, xv.z);
    kk[3] = fmaf(pv.w - xv.w, k4.w, xv.w);
    rr[0] = fmaf(pv.x - xv.x, r4.x, xv.x);
    rr[1] = fmaf(pv.y - xv.y, r4.y, xv.y);
    rr[2] = fmaf(pv.z - xv.z, r4.z, xv.z);
    rr[3] = fmaf(pv.w - xv.w, r4.w, xv.w);

    xk[idx] = make_uint2(ph2(__float2half_rn(kk[0]), __float2half_rn(kk[1])),
                         ph2(__float2half_rn(kk[2]), __float2half_rn(kk[3])));
    xr[idx] = make_uint2(ph2(__float2half_rn(rr[0]), __float2half_rn(rr[1])),
                         ph2(__float2half_rn(rr[2]), __float2half_rn(rr[3])));
}

__global__ void cvt_kernel(const float4* __restrict__ in,
                           uint4* __restrict__ oh, size_t n8) {
    size_t i = (size_t)blockIdx.x * blockDim.x + threadIdx.x;
    if (i >= n8) return;
    float4 a = in[2 * i], b = in[2 * i + 1];
    oh[i] = make_uint4(ph2(__float2half_rn(a.x), __float2half_rn(a.y)),
                       ph2(__float2half_rn(a.z), __float2half_rn(a.w)),
                       ph2(__float2half_rn(b.x), __float2half_rn(b.y)),
                       ph2(__float2half_rn(b.z), __float2half_rn(b.w)));
}

__global__ void state_kernel(const float* __restrict__ x, float* __restrict__ outs) {
    int idx = blockIdx.x * blockDim.x + threadIdx.x;
    int b = idx / CDIM;
    int c = idx % CDIM;
    outs[idx] = x[((size_t)b * TDIM + (TDIM - 1)) * CDIM + c];
}

// ---------------- fp16 HMMA GEMM (all three GEMMs) ---------------------------
// C[M,N] = A[M,K] * B[N,K]^T, fp16 inputs, fp32 accum.
// CTA 128x256, 16 warps (512 thr), warp 64x32, BK=32, 8-stage cp.async
// (wait_group 6), XOR-swizzled 64B rows.
// epi 0: relu^2->fp16 | 1: sigmoid->fp32 | 2: *Rm->fp32
#define ASEC   (128 * 64)            // 8192
#define BSEC   (256 * 64)            // 16384
#define STAGE1 (ASEC + BSEC)         // 24576
#define NST1   8
#define SMEM1  (NST1 * STAGE1)       // 196608

__global__ void __launch_bounds__(512, 1)
gemm_f16(const __half* __restrict__ A, const __half* __restrict__ B,
         int N, int K, int Ntiles, int epi,
         float* __restrict__ Cf, __half* __restrict__ Chf,
         const float* __restrict__ Rm) {
    extern __shared__ char smem[];
    const uint32_t sb = smem_u32(smem);
    const int tid  = threadIdx.x;
    const int wid  = tid >> 5;
    const int lane = tid & 31;
    const int wm   = wid & 1;        // 2 warp-rows (64 each)
    const int wn   = wid >> 1;       // 8 warp-cols (32 each)

    // band-swizzled tile mapping (bands of 16 M-tiles)
    int bid = blockIdx.x;
    int bandCtas = 16 * Ntiles;
    int band = bid / bandCtas, rmd = bid % bandCtas;
    int nt = rmd >> 4;
    int mt = band * 16 + (rmd & 15);
    const size_t m0 = (size_t)mt * 128;
    const size_t n0 = (size_t)nt * 256;

    const size_t K2 = (size_t)K * 2;
    const char* pA = (const char*)(A + m0 * (size_t)K);
    const char* pB = (const char*)(B + n0 * (size_t)K);

    const int nk = K >> 5;   // BK = 32

    const int cr = tid >> 2;
    const int cc = tid & 3;
    const uint32_t aoff  = swoff(cr, cc);
    const uint32_t boff0 = swoff(cr, cc);
    const uint32_t boff1 = swoff(cr + 128, cc);

    // prologue: stages 0..6
#pragma unroll
    for (int s = 0; s < 7; ++s) {
        const uint32_t base = sb + s * STAGE1;
        const size_t kb = (size_t)s * 64;
        size_t g  = (size_t)cr * K2 + kb + (size_t)cc * 16;
        size_t g1 = (size_t)(cr + 128) * K2 + kb + (size_t)cc * 16;
        cpa16(base + aoff, pA + g);
        cpa16(base + ASEC + boff0, pB + g);
        cpa16(base + ASEC + boff1, pB + g1);
        asm volatile("cp.async.commit_group;" ::: "memory");
    }

    float acc[4][4][4];
#pragma unroll
    for (int i = 0; i < 4; ++i)
#pragma unroll
        for (int j = 0; j < 4; ++j)
#pragma unroll
            for (int q = 0; q < 4; ++q) acc[i][j][q] = 0.0f;

    const int rl_a   = (lane & 7) + ((lane >> 3) & 1) * 8;
    const int sel_a  = (rl_a >> 1) & 3;
    const int cb_a   = lane >> 4;
    const uint32_t arow  = (uint32_t)(rl_a * 64);
    const uint32_t acol0 = (uint32_t)(((0 + cb_a) ^ sel_a) << 4);
    const uint32_t acol1 = (uint32_t)(((2 + cb_a) ^ sel_a) << 4);

    const int rl_b   = (lane & 7) + (lane >> 4) * 8;
    const int sel_b  = (rl_b >> 1) & 3;
    const int cb_b   = (lane >> 3) & 1;
    const uint32_t brow  = (uint32_t)(rl_b * 64);
    const uint32_t bcol0 = (uint32_t)(((0 + cb_b) ^ sel_b) << 4);
    const uint32_t bcol1 = (uint32_t)(((2 + cb_b) ^ sel_b) << 4);

    int stC = 0, stP = 7;
    for (int kt = 0; kt < nk; ++kt) {
        asm volatile("cp.async.wait_group 6;" ::: "memory");
        __syncthreads();

        if (kt + 7 < nk) {
            const uint32_t base = sb + stP * STAGE1;
            const size_t kb = (size_t)(kt + 7) * 64;
            size_t g  = (size_t)cr * K2 + kb + (size_t)cc * 16;
            size_t g1 = (size_t)(cr + 128) * K2 + kb + (size_t)cc * 16;
            cpa16(base + aoff, pA + g);
            cpa16(base + ASEC + boff0, pB + g);
            cpa16(base + ASEC + boff1, pB + g1);
        }
        asm volatile("cp.async.commit_group;" ::: "memory");

        const uint32_t sbase = sb + stC * STAGE1;
        const uint32_t aS = sbase;
        const uint32_t bS = sbase + ASEC;

#pragma unroll
        for (int kk = 0; kk < 2; ++kk) {
            const uint32_t acol = kk ? acol1 : acol0;
            const uint32_t bcol = kk ? bcol1 : bcol0;
            uint32_t af[4][4], bf[4][2];
#pragma unroll
            for (int mi = 0; mi < 4; ++mi) {
                uint32_t ra = (uint32_t)((wm * 64 + mi * 16) * 64) + arow + acol;
                ldsm4(af[mi][0], af[mi][1], af[mi][2], af[mi][3], aS + ra);
            }
#pragma unroll
            for (int nj = 0; nj < 2; ++nj) {
                uint32_t rb = (uint32_t)((wn * 32 + nj * 16) * 64) + brow + bcol;
                uint32_t t0, t1, t2, t3;
                ldsm4(t0, t1, t2, t3, bS + rb);
                bf[nj * 2][0] = t0; bf[nj * 2][1] = t1;
                bf[nj * 2 + 1][0] = t2; bf[nj * 2 + 1][1] = t3;
            }
#pragma unroll
            for (int mi = 0; mi < 4; ++mi)
#pragma unroll
                for (int ni = 0; ni < 4; ++ni)
                    mma_f16(acc[mi][ni], af[mi], bf[ni]);
        }

        if (++stC == NST1) stC = 0;
        if (++stP == NST1) stP = 0;
    }

    // ---- epilogue ----
    const size_t mw = m0 + wm * 64;
    const size_t nw = n0 + wn * 32;
    const int tr = lane >> 2;
    const int tc = (lane & 3) * 2;
#pragma unroll
    for (int mi = 0; mi < 4; ++mi)
#pragma unroll
        for (int nj = 0; nj < 4; ++nj) {
            const float* c = acc[mi][nj];
            const size_t row = mw + mi * 16 + tr;
            const size_t col = nw + nj * 8 + tc;
#pragma unroll
            for (int h = 0; h < 2; ++h) {
                const size_t base = (row + h * 8) * (size_t)N + col;
                float v0 = c[h * 2], v1 = c[h * 2 + 1];
                if (epi == 0) {                 // relu^2 -> fp16
                    v0 = fmaxf(v0, 0.0f); v0 *= v0;
                    v1 = fmaxf(v1, 0.0f); v1 *= v1;
                    *reinterpret_cast<uint32_t*>(Chf + base) =
                        ph2(__float2half_rn(v0), __float2half_rn(v1));
                } else if (epi == 1) {          // sigmoid -> fp32
                    float2 o;
                    o.x = 1.0f / (1.0f + expf(-v0));
                    o.y = 1.0f / (1.0f + expf(-v1));
                    *reinterpret_cast<float2*>(Cf + base) = o;
                } else {                        // * r -> fp32
                    float2 rv = *reinterpret_cast<const float2*>(Rm + base);
                    float2 o;
                    o.x = v0 * rv.x;
                    o.y = v1 * rv.y;
                    *reinterpret_cast<float2*>(Cf + base) = o;
                }
            }
        }
}

// ---------------- launch -----------------------------------------------------
extern "C" void kernel_launch(void* const* d_in, const int* in_sizes, int n_in,
                              void* d_out, int out_size) {
    const float* x  = (const float*)d_in[0];
    const float* ls = (const float*)d_in[1];
    const float* mk = (const float*)d_in[2];
    const float* mr = (const float*)d_in[3];
    const float* kw = (const float*)d_in[4];   // (F, C)
    const float* rw = (const float*)d_in[5];   // (C, C)
    const float* vw = (const float*)d_in[6];   // (C, F)
    float* out = (float*)d_out;

    __half *xk, *xr, *s, *kwp, *rwp, *vwp;
    float* r;
    cudaGetSymbolAddress((void**)&xk,  g_xk);
    cudaGetSymbolAddress((void**)&xr,  g_xr);
    cudaGetSymbolAddress((void**)&s,   g_s);
    cudaGetSymbolAddress((void**)&kwp, g_kw);
    cudaGetSymbolAddress((void**)&rwp, g_rw);
    cudaGetSymbolAddress((void**)&vwp, g_vw);
    cudaGetSymbolAddress((void**)&r,   g_r);

    cudaFuncSetAttribute(gemm_f16, cudaFuncAttributeMaxDynamicSharedMemorySize, SMEM1);

    // 1) token-shift mix -> fp16 xk, xr
    mix_kernel<<<(MDIM * (CDIM / 4)) / 256, 256>>>(
        (const float4*)x, (const float4*)ls, (const float4*)mk, (const float4*)mr,
        (uint2*)xk, (uint2*)xr);

    // 2) weight prep: all single fp16
    {
        size_t n8;
        n8 = (size_t)FDIM * CDIM / 8;
        cvt_kernel<<<(unsigned)((n8 + 255) / 256), 256>>>((const float4*)kw, (uint4*)kwp, n8);
        n8 = (size_t)CDIM * CDIM / 8;
        cvt_kernel<<<(unsigned)((n8 + 255) / 256), 256>>>((const float4*)rw, (uint4*)rwp, n8);
        n8 = (size_t)CDIM * FDIM / 8;
        cvt_kernel<<<(unsigned)((n8 + 255) / 256), 256>>>((const float4*)vw, (uint4*)vwp, n8);
    }

    // 3) S = relu(xk @ Kw^T)^2 -> fp16           [M=8192, N=14336, K=4096]
    gemm_f16<<<(MDIM / 128) * (FDIM / 256), 512, SMEM1>>>(
        xk, kwp, FDIM, CDIM, FDIM / 256, 0, nullptr, s, nullptr);

    // 4) R = sigmoid(xr @ Rw^T) -> fp32          [M=8192, N=4096, K=4096]
    gemm_f16<<<(MDIM / 128) * (CDIM / 256), 512, SMEM1>>>(
        xr, rwp, CDIM, CDIM, CDIM / 256, 1, r, nullptr, nullptr);

    // 5) out = R * (S @ Vw^T)  -> fp32           [M=8192, N=4096, K=14336]
    gemm_f16<<<(MDIM / 128) * (CDIM / 256), 512, SMEM1>>>(
        s, vwp, CDIM, FDIM, CDIM / 256, 2, out, nullptr, r);

    // 6) new_state = x[:, -1, :]
    state_kernel<<<(BDIM * CDIM) / 256, 256>>>(x, out + (size_t)MDIM * CDIM);
}

// round 14
// speedup vs baseline: 1.1583x; 1.1203x over previous
#include <cuda_runtime.h>
#include <cuda_fp16.h>
#include <cstdint>
#include <math.h>

#define BDIM 4
#define TDIM 2048
#define CDIM 4096
#define FDIM 14336
#define MDIM (BDIM * TDIM)   // 8192

// ---------------- scratch (device globals; allocation-free rule) -----------
__device__ __half g_xk [(size_t)MDIM * CDIM];
__device__ __half g_xr [(size_t)MDIM * CDIM];
__device__ __half g_s  [(size_t)MDIM * FDIM];
__device__ __half g_kw [(size_t)FDIM * CDIM];
__device__ __half g_rw [(size_t)CDIM * CDIM];
__device__ __half g_vw [(size_t)CDIM * FDIM];
__device__ float  g_r  [(size_t)MDIM * CDIM];

// ---------------- helpers ----------------------------------------------------
__device__ __forceinline__ uint32_t smem_u32(const void* p) {
    uint32_t a;
    asm("{ .reg .u64 t; cvta.to.shared.u64 t, %1; cvt.u32.u64 %0, t; }" : "=r"(a) : "l"(p));
    return a;
}
__device__ __forceinline__ void cpa16(uint32_t dst, const void* src) {
    asm volatile("cp.async.cg.shared.global [%0], [%1], 16;" :: "r"(dst), "l"(src));
}
__device__ __forceinline__ void ldsm4(uint32_t& r0, uint32_t& r1, uint32_t& r2, uint32_t& r3,
                                      uint32_t addr) {
    asm volatile("ldmatrix.sync.aligned.m8n8.x4.shared.b16 {%0,%1,%2,%3}, [%4];"
                 : "=r"(r0), "=r"(r1), "=r"(r2), "=r"(r3) : "r"(addr));
}
__device__ __forceinline__ void mma_f16(float* c, const uint32_t* a, const uint32_t* b) {
    asm volatile(
        "mma.sync.aligned.m16n8k16.row.col.f32.f16.f16.f32 "
        "{%0,%1,%2,%3}, {%4,%5,%6,%7}, {%8,%9}, {%0,%1,%2,%3};"
        : "+f"(c[0]), "+f"(c[1]), "+f"(c[2]), "+f"(c[3])
        : "r"(a[0]), "r"(a[1]), "r"(a[2]), "r"(a[3]), "r"(b[0]), "r"(b[1]));
}
__device__ __forceinline__ uint32_t ph2(__half a, __half b) {
    __half2 t = __halves2half2(a, b);
    return *reinterpret_cast<uint32_t*>(&t);
}

// 64B-row XOR swizzle: 16B chunk c at row r stored at chunk (c ^ ((r>>1)&3))
__device__ __forceinline__ uint32_t swoff(int r, int c) {
    return (uint32_t)(r * 64 + ((c ^ ((r >> 1) & 3)) << 4));
}

// ---------------- elementwise kernels ---------------------------------------
__global__ void mix_kernel(const float4* __restrict__ x,
                           const float4* __restrict__ ls,
                           const float4* __restrict__ mk,
                           const float4* __restrict__ mr,
                           uint2* __restrict__ xk, uint2* __restrict__ xr) {
    const int C4 = CDIM / 4;
    int idx = blockIdx.x * blockDim.x + threadIdx.x;
    int c4 = idx % C4;
    int bt = idx / C4;
    int t  = bt % TDIM;
    int b  = bt / TDIM;

    float4 xv = x[idx];
    float4 pv = (t == 0) ? ls[b * C4 + c4] : x[idx - C4];
    float4 k4 = mk[c4];
    float4 r4 = mr[c4];

    float kk[4], rr[4];
    kk[0] = fmaf(pv.x - xv.x, k4.x, xv.x);
    kk[1] = fmaf(pv.y - xv.y, k4.y, xv.y);
    kk[2] = fmaf(pv.z - xv.z, k4.z, xv.z);
    kk[3] = fmaf(pv.w - xv.w, k4.w, xv.w);
    rr[0] = fmaf(pv.x - xv.x, r4.x, xv.x);
    rr[1] = fmaf(pv.y - xv.y, r4.y, xv.y);
    rr[2] = fmaf(pv.z - xv.z, r4.z, xv.z);
    rr[3] = fmaf(pv.w - xv.w, r4.w, xv.w);

    xk[idx] = make_uint2(ph2(__float2half_rn(kk[0]), __float2half_rn(kk[1])),
                         ph2(__float2half_rn(kk[2]), __float2half_rn(kk[3])));
    xr[idx] = make_uint2(ph2(__float2half_rn(rr[0]), __float2half_rn(rr[1])),
                         ph2(__float2half_rn(rr[2]), __float2half_rn(rr[3])));
}

__global__ void cvt_kernel(const float4* __restrict__ in,
                           uint4* __restrict__ oh, size_t n8) {
    size_t i = (size_t)blockIdx.x * blockDim.x + threadIdx.x;
    if (i >= n8) return;
    float4 a = in[2 * i], b = in[2 * i + 1];
    oh[i] = make_uint4(ph2(__float2half_rn(a.x), __float2half_rn(a.y)),
                       ph2(__float2half_rn(a.z), __float2half_rn(a.w)),
                       ph2(__float2half_rn(b.x), __float2half_rn(b.y)),
                       ph2(__float2half_rn(b.z), __float2half_rn(b.w)));
}

__global__ void state_kernel(const float* __restrict__ x, float* __restrict__ outs) {
    int idx = blockIdx.x * blockDim.x + threadIdx.x;
    int b = idx / CDIM;
    int c = idx % CDIM;
    outs[idx] = x[((size_t)b * TDIM + (TDIM - 1)) * CDIM + c];
}

// ---------------- fp16 HMMA GEMM (all three GEMMs) ---------------------------
// C[M,N] = A[M,K] * B[N,K]^T, fp16 inputs, fp32 accum.
// CTA 128x128, 8 warps (256 thr), warp 64x32 (2x4), BK=32, 6-stage cp.async
// (wait_group 4), XOR-swizzled 64B rows. 2 CTAs/SM (96KB smem, <=128 regs).
// epi 0: relu^2->fp16 | 1: sigmoid->fp32 | 2: *Rm->fp32
#define ASEC   (128 * 64)            // 8192
#define BSEC   (128 * 64)            // 8192
#define STAGE1 (ASEC + BSEC)         // 16384
#define NST1   6
#define SMEM1  (NST1 * STAGE1)       // 98304

__global__ void __launch_bounds__(256, 2)
gemm_f16(const __half* __restrict__ A, const __half* __restrict__ B,
         int N, int K, int Ntiles, int epi,
         float* __restrict__ Cf, __half* __restrict__ Chf,
         const float* __restrict__ Rm) {
    extern __shared__ char smem[];
    const uint32_t sb = smem_u32(smem);
    const int tid  = threadIdx.x;
    const int wid  = tid >> 5;
    const int lane = tid & 31;
    const int wm   = wid & 1;        // 2 warp-rows (64 each)
    const int wn   = wid >> 1;       // 4 warp-cols (32 each)

    // band-swizzled tile mapping (bands of 16 M-tiles)
    int bid = blockIdx.x;
    int bandCtas = 16 * Ntiles;
    int band = bid / bandCtas, rmd = bid % bandCtas;
    int nt = rmd >> 4;
    int mt = band * 16 + (rmd & 15);
    const size_t m0 = (size_t)mt * 128;
    const size_t n0 = (size_t)nt * 128;

    const size_t K2 = (size_t)K * 2;
    const char* pA = (const char*)(A + m0 * (size_t)K);
    const char* pB = (const char*)(B + n0 * (size_t)K);

    const int nk = K >> 5;   // BK = 32

    // loader coords (256 threads): A 512 chunks (2/thread), B 512 (2/thread)
    const int cr = tid >> 2;          // row 0..63
    const int cc = tid & 3;           // 16B chunk in row

    const uint32_t off0 = swoff(cr, cc);
    const uint32_t off1 = swoff(cr + 64, cc);

    // prologue: stages 0..4
#pragma unroll
    for (int s = 0; s < 5; ++s) {
        const uint32_t base = sb + s * STAGE1;
        const size_t kb = (size_t)s * 64;
        size_t g0 = (size_t)cr * K2 + kb + (size_t)cc * 16;
        size_t g1 = (size_t)(cr + 64) * K2 + kb + (size_t)cc * 16;
        cpa16(base + off0,        pA + g0);
        cpa16(base + off1,        pA + g1);
        cpa16(base + ASEC + off0, pB + g0);
        cpa16(base + ASEC + off1, pB + g1);
        asm volatile("cp.async.commit_group;" ::: "memory");
    }

    float acc[4][4][4];
#pragma unroll
    for (int i = 0; i < 4; ++i)
#pragma unroll
        for (int j = 0; j < 4; ++j)
#pragma unroll
            for (int q = 0; q < 4; ++q) acc[i][j][q] = 0.0f;

    const int rl_a   = (lane & 7) + ((lane >> 3) & 1) * 8;
    const int sel_a  = (rl_a >> 1) & 3;
    const int cb_a   = lane >> 4;
    const uint32_t arow  = (uint32_t)(rl_a * 64);
    const uint32_t acol0 = (uint32_t)(((0 + cb_a) ^ sel_a) << 4);
    const uint32_t acol1 = (uint32_t)(((2 + cb_a) ^ sel_a) << 4);

    const int rl_b   = (lane & 7) + (lane >> 4) * 8;
    const int sel_b  = (rl_b >> 1) & 3;
    const int cb_b   = (lane >> 3) & 1;
    const uint32_t brow  = (uint32_t)(rl_b * 64);
    const uint32_t bcol0 = (uint32_t)(((0 + cb_b) ^ sel_b) << 4);
    const uint32_t bcol1 = (uint32_t)(((2 + cb_b) ^ sel_b) << 4);

    int stC = 0, stP = 5;
    for (int kt = 0; kt < nk; ++kt) {
        asm volatile("cp.async.wait_group 4;" ::: "memory");
        __syncthreads();

        if (kt + 5 < nk) {
            const uint32_t base = sb + stP * STAGE1;
            const size_t kb = (size_t)(kt + 5) * 64;
            size_t g0 = (size_t)cr * K2 + kb + (size_t)cc * 16;
            size_t g1 = (size_t)(cr + 64) * K2 + kb + (size_t)cc * 16;
            cpa16(base + off0,        pA + g0);
            cpa16(base + off1,        pA + g1);
            cpa16(base + ASEC + off0, pB + g0);
            cpa16(base + ASEC + off1, pB + g1);
        }
        asm volatile("cp.async.commit_group;" ::: "memory");

        const uint32_t sbase = sb + stC * STAGE1;
        const uint32_t aS = sbase;
        const uint32_t bS = sbase + ASEC;

#pragma unroll
        for (int kk = 0; kk < 2; ++kk) {
            const uint32_t acol = kk ? acol1 : acol0;
            const uint32_t bcol = kk ? bcol1 : bcol0;
            uint32_t af[4][4], bf[4][2];
#pragma unroll
            for (int mi = 0; mi < 4; ++mi) {
                uint32_t ra = (uint32_t)((wm * 64 + mi * 16) * 64) + arow + acol;
                ldsm4(af[mi][0], af[mi][1], af[mi][2], af[mi][3], aS + ra);
            }
#pragma unroll
            for (int nj = 0; nj < 2; ++nj) {
                uint32_t rb = (uint32_t)((wn * 32 + nj * 16) * 64) + brow + bcol;
                uint32_t t0, t1, t2, t3;
                ldsm4(t0, t1, t2, t3, bS + rb);
                bf[nj * 2][0] = t0; bf[nj * 2][1] = t1;
                bf[nj * 2 + 1][0] = t2; bf[nj * 2 + 1][1] = t3;
            }
#pragma unroll
            for (int mi = 0; mi < 4; ++mi)
#pragma unroll
                for (int ni = 0; ni < 4; ++ni)
                    mma_f16(acc[mi][ni], af[mi], bf[ni]);
        }

        if (++stC == NST1) stC = 0;
        if (++stP == NST1) stP = 0;
    }

    // ---- epilogue ----
    const size_t mw = m0 + wm * 64;
    const size_t nw = n0 + wn * 32;
    const int tr = lane >> 2;
    const int tc = (lane & 3) * 2;
#pragma unroll
    for (int mi = 0; mi < 4; ++mi)
#pragma unroll
        for (int nj = 0; nj < 4; ++nj) {
            const float* c = acc[mi][nj];
            const size_t row = mw + mi * 16 + tr;
            const size_t col = nw + nj * 8 + tc;
#pragma unroll
            for (int h = 0; h < 2; ++h) {
                const size_t base = (row + h * 8) * (size_t)N + col;
                float v0 = c[h * 2], v1 = c[h * 2 + 1];
                if (epi == 0) {                 // relu^2 -> fp16
                    v0 = fmaxf(v0, 0.0f); v0 *= v0;
                    v1 = fmaxf(v1, 0.0f); v1 *= v1;
                    *reinterpret_cast<uint32_t*>(Chf + base) =
                        ph2(__float2half_rn(v0), __float2half_rn(v1));
                } else if (epi == 1) {          // sigmoid -> fp32
                    float2 o;
                    o.x = 1.0f / (1.0f + expf(-v0));
                    o.y = 1.0f / (1.0f + expf(-v1));
                    *reinterpret_cast<float2*>(Cf + base) = o;
                } else {                        // * r -> fp32
                    float2 rv = *reinterpret_cast<const float2*>(Rm + base);
                    float2 o;
                    o.x = v0 * rv.x;
                    o.y = v1 * rv.y;
                    *reinterpret_cast<float2*>(Cf + base) = o;
                }
            }
        }
}

// ---------------- launch -----------------------------------------------------
extern "C" void kernel_launch(void* const* d_in, const int* in_sizes, int n_in,
                              void* d_out, int out_size) {
    const float* x  = (const float*)d_in[0];
    const float* ls = (const float*)d_in[1];
    const float* mk = (const float*)d_in[2];
    const float* mr = (const float*)d_in[3];
    const float* kw = (const float*)d_in[4];   // (F, C)
    const float* rw = (const float*)d_in[5];   // (C, C)
    const float* vw = (const float*)d_in[6];   // (C, F)
    float* out = (float*)d_out;

    __half *xk, *xr, *s, *kwp, *rwp, *vwp;
    float* r;
    cudaGetSymbolAddress((void**)&xk,  g_xk);
    cudaGetSymbolAddress((void**)&xr,  g_xr);
    cudaGetSymbolAddress((void**)&s,   g_s);
    cudaGetSymbolAddress((void**)&kwp, g_kw);
    cudaGetSymbolAddress((void**)&rwp, g_rw);
    cudaGetSymbolAddress((void**)&vwp, g_vw);
    cudaGetSymbolAddress((void**)&r,   g_r);

    cudaFuncSetAttribute(gemm_f16, cudaFuncAttributeMaxDynamicSharedMemorySize, SMEM1);

    // 1) token-shift mix -> fp16 xk, xr
    mix_kernel<<<(MDIM * (CDIM / 4)) / 256, 256>>>(
        (const float4*)x, (const float4*)ls, (const float4*)mk, (const float4*)mr,
        (uint2*)xk, (uint2*)xr);

    // 2) weight prep: all single fp16
    {
        size_t n8;
        n8 = (size_t)FDIM * CDIM / 8;
        cvt_kernel<<<(unsigned)((n8 + 255) / 256), 256>>>((const float4*)kw, (uint4*)kwp, n8);
        n8 = (size_t)CDIM * CDIM / 8;
        cvt_kernel<<<(unsigned)((n8 + 255) / 256), 256>>>((const float4*)rw, (uint4*)rwp, n8);
        n8 = (size_t)CDIM * FDIM / 8;
        cvt_kernel<<<(unsigned)((n8 + 255) / 256), 256>>>((const float4*)vw, (uint4*)vwp, n8);
    }

    // 3) S = relu(xk @ Kw^T)^2 -> fp16           [M=8192, N=14336, K=4096]
    gemm_f16<<<(MDIM / 128) * (FDIM / 128), 256, SMEM1>>>(
        xk, kwp, FDIM, CDIM, FDIM / 128, 0, nullptr, s, nullptr);

    // 4) R = sigmoid(xr @ Rw^T) -> fp32          [M=8192, N=4096, K=4096]
    gemm_f16<<<(MDIM / 128) * (CDIM / 128), 256, SMEM1>>>(
        xr, rwp, CDIM, CDIM, CDIM / 128, 1, r, nullptr, nullptr);

    // 5) out = R * (S @ Vw^T)  -> fp32           [M=8192, N=4096, K=14336]
    gemm_f16<<<(MDIM / 128) * (CDIM / 128), 256, SMEM1>>>(
        s, vwp, CDIM, FDIM, CDIM / 128, 2, out, nullptr, r);

    // 6) new_state = x[:, -1, :]
    state_kernel<<<(BDIM * CDIM) / 256, 256>>>(x, out + (size_t)MDIM * CDIM);
}

// round 15
// speedup vs baseline: 1.2526x; 1.0814x over previous
#include <cuda_runtime.h>
#include <cuda_fp16.h>
#include <cstdint>
#include <math.h>

#define BDIM 4
#define TDIM 2048
#define CDIM 4096
#define FDIM 14336
#define MDIM (BDIM * TDIM)   // 8192

// ---------------- scratch (device globals; allocation-free rule) -----------
__device__ __half g_xk [(size_t)MDIM * CDIM];
__device__ __half g_xr [(size_t)MDIM * CDIM];
__device__ __half g_s  [(size_t)MDIM * FDIM];
__device__ __half g_kw [(size_t)FDIM * CDIM];
__device__ __half g_rw [(size_t)CDIM * CDIM];
__device__ __half g_vw [(size_t)CDIM * FDIM];
__device__ float  g_r  [(size_t)MDIM * CDIM];

// ---------------- helpers ----------------------------------------------------
__device__ __forceinline__ uint32_t smem_u32(const void* p) {
    uint32_t a;
    asm("{ .reg .u64 t; cvta.to.shared.u64 t, %1; cvt.u32.u64 %0, t; }" : "=r"(a) : "l"(p));
    return a;
}
__device__ __forceinline__ void cpa16(uint32_t dst, const void* src) {
    asm volatile("cp.async.cg.shared.global [%0], [%1], 16;" :: "r"(dst), "l"(src));
}
__device__ __forceinline__ void ldsm4(uint32_t& r0, uint32_t& r1, uint32_t& r2, uint32_t& r3,
                                      uint32_t addr) {
    asm volatile("ldmatrix.sync.aligned.m8n8.x4.shared.b16 {%0,%1,%2,%3}, [%4];"
                 : "=r"(r0), "=r"(r1), "=r"(r2), "=r"(r3) : "r"(addr));
}
__device__ __forceinline__ void mma_f16(float* c, const uint32_t* a, const uint32_t* b) {
    asm volatile(
        "mma.sync.aligned.m16n8k16.row.col.f32.f16.f16.f32 "
        "{%0,%1,%2,%3}, {%4,%5,%6,%7}, {%8,%9}, {%0,%1,%2,%3};"
        : "+f"(c[0]), "+f"(c[1]), "+f"(c[2]), "+f"(c[3])
        : "r"(a[0]), "r"(a[1]), "r"(a[2]), "r"(a[3]), "r"(b[0]), "r"(b[1]));
}
__device__ __forceinline__ uint32_t ph2(__half a, __half b) {
    __half2 t = __halves2half2(a, b);
    return *reinterpret_cast<uint32_t*>(&t);
}

// 64B-row XOR swizzle: 16B chunk c at row r stored at chunk (c ^ ((r>>1)&3))
__device__ __forceinline__ uint32_t swoff(int r, int c) {
    return (uint32_t)(r * 64 + ((c ^ ((r >> 1) & 3)) << 4));
}

// ---------------- elementwise kernels ---------------------------------------
// mix + state fused: last block handles new_state copy
__global__ void mix_kernel(const float4* __restrict__ x,
                           const float4* __restrict__ ls,
                           const float4* __restrict__ mk,
                           const float4* __restrict__ mr,
                           uint2* __restrict__ xk, uint2* __restrict__ xr,
                           float4* __restrict__ outs) {
    const int C4 = CDIM / 4;
    int idx = blockIdx.x * blockDim.x + threadIdx.x;
    int c4 = idx % C4;
    int bt = idx / C4;
    int t  = bt % TDIM;
    int b  = bt / TDIM;

    float4 xv = x[idx];
    float4 pv = (t == 0) ? ls[b * C4 + c4] : x[idx - C4];
    float4 k4 = mk[c4];
    float4 r4 = mr[c4];

    float kk[4], rr[4];
    kk[0] = fmaf(pv.x - xv.x, k4.x, xv.x);
    kk[1] = fmaf(pv.y - xv.y, k4.y, xv.y);
    kk[2] = fmaf(pv.z - xv.z, k4.z, xv.z);
    kk[3] = fmaf(pv.w - xv.w, k4.w, xv.w);
    rr[0] = fmaf(pv.x - xv.x, r4.x, xv.x);
    rr[1] = fmaf(pv.y - xv.y, r4.y, xv.y);
    rr[2] = fmaf(pv.z - xv.z, r4.z, xv.z);
    rr[3] = fmaf(pv.w - xv.w, r4.w, xv.w);

    xk[idx] = make_uint2(ph2(__float2half_rn(kk[0]), __float2half_rn(kk[1])),
                         ph2(__float2half_rn(kk[2]), __float2half_rn(kk[3])));
    xr[idx] = make_uint2(ph2(__float2half_rn(rr[0]), __float2half_rn(rr[1])),
                         ph2(__float2half_rn(rr[2]), __float2half_rn(rr[3])));

    // new_state: x[:, T-1, :] (fused; t==T-1 rows copy themselves)
    if (t == TDIM - 1)
        outs[b * C4 + c4] = xv;
}

__global__ void cvt_kernel(const float4* __restrict__ in,
                           uint4* __restrict__ oh, size_t n8) {
    size_t i = (size_t)blockIdx.x * blockDim.x + threadIdx.x;
    if (i >= n8) return;
    float4 a = in[2 * i], b = in[2 * i + 1];
    oh[i] = make_uint4(ph2(__float2half_rn(a.x), __float2half_rn(a.y)),
                       ph2(__float2half_rn(a.z), __float2half_rn(a.w)),
                       ph2(__float2half_rn(b.x), __float2half_rn(b.y)),
                       ph2(__float2half_rn(b.z), __float2half_rn(b.w)));
}

// ---------------- fp16 HMMA GEMM (all three GEMMs) ---------------------------
// C[M,N] = A[M,K] * B[N,K]^T, fp16 inputs, fp32 accum.
// CTA 128x128, 8 warps (256 thr), warp 64x32 (2x4), BK=32, 6-stage cp.async
// (wait_group 4), XOR-swizzled 64B rows, 2 CTAs/SM.
// Prefetch cp.asyncs issued BETWEEN kk=0 and kk=1 to smooth LSU pressure.
// epi 0: relu^2->fp16 | 1: sigmoid->fp32 | 2: *Rm->fp32
#define ASEC   (128 * 64)            // 8192
#define BSEC   (128 * 64)            // 8192
#define STAGE1 (ASEC + BSEC)         // 16384
#define NST1   6
#define SMEM1  (NST1 * STAGE1)       // 98304

__global__ void __launch_bounds__(256, 2)
gemm_f16(const __half* __restrict__ A, const __half* __restrict__ B,
         int N, int K, int Ntiles, int epi,
         float* __restrict__ Cf, __half* __restrict__ Chf,
         const float* __restrict__ Rm) {
    extern __shared__ char smem[];
    const uint32_t sb = smem_u32(smem);
    const int tid  = threadIdx.x;
    const int wid  = tid >> 5;
    const int lane = tid & 31;
    const int wm   = wid & 1;        // 2 warp-rows (64 each)
    const int wn   = wid >> 1;       // 4 warp-cols (32 each)

    // band-swizzled tile mapping (bands of 16 M-tiles)
    int bid = blockIdx.x;
    int bandCtas = 16 * Ntiles;
    int band = bid / bandCtas, rmd = bid % bandCtas;
    int nt = rmd >> 4;
    int mt = band * 16 + (rmd & 15);
    const size_t m0 = (size_t)mt * 128;
    const size_t n0 = (size_t)nt * 128;

    const size_t K2 = (size_t)K * 2;
    const char* pA = (const char*)(A + m0 * (size_t)K);
    const char* pB = (const char*)(B + n0 * (size_t)K);

    const int nk = K >> 5;   // BK = 32

    const int cr = tid >> 2;          // row 0..63
    const int cc = tid & 3;           // 16B chunk in row
    const uint32_t off0 = swoff(cr, cc);
    const uint32_t off1 = swoff(cr + 64, cc);

    // prologue: stages 0..4
#pragma unroll
    for (int s = 0; s < 5; ++s) {
        const uint32_t base = sb + s * STAGE1;
        const size_t kb = (size_t)s * 64;
        size_t g0 = (size_t)cr * K2 + kb + (size_t)cc * 16;
        size_t g1 = (size_t)(cr + 64) * K2 + kb + (size_t)cc * 16;
        cpa16(base + off0,        pA + g0);
        cpa16(base + off1,        pA + g1);
        cpa16(base + ASEC + off0, pB + g0);
        cpa16(base + ASEC + off1, pB + g1);
        asm volatile("cp.async.commit_group;" ::: "memory");
    }

    float acc[4][4][4];
#pragma unroll
    for (int i = 0; i < 4; ++i)
#pragma unroll
        for (int j = 0; j < 4; ++j)
#pragma unroll
            for (int q = 0; q < 4; ++q) acc[i][j][q] = 0.0f;

    const int rl_a   = (lane & 7) + ((lane >> 3) & 1) * 8;
    const int sel_a  = (rl_a >> 1) & 3;
    const int cb_a   = lane >> 4;
    const uint32_t arow  = (uint32_t)(rl_a * 64);
    const uint32_t acol0 = (uint32_t)(((0 + cb_a) ^ sel_a) << 4);
    const uint32_t acol1 = (uint32_t)(((2 + cb_a) ^ sel_a) << 4);

    const int rl_b   = (lane & 7) + (lane >> 4) * 8;
    const int sel_b  = (rl_b >> 1) & 3;
    const int cb_b   = (lane >> 3) & 1;
    const uint32_t brow  = (uint32_t)(rl_b * 64);
    const uint32_t bcol0 = (uint32_t)(((0 + cb_b) ^ sel_b) << 4);
    const uint32_t bcol1 = (uint32_t)(((2 + cb_b) ^ sel_b) << 4);

    int stC = 0, stP = 5;
    for (int kt = 0; kt < nk; ++kt) {
        asm volatile("cp.async.wait_group 4;" ::: "memory");
        __syncthreads();

        const uint32_t sbase = sb + stC * STAGE1;
        const uint32_t aS = sbase;
        const uint32_t bS = sbase + ASEC;

        // ---- kk = 0: LDSM + MMA first (no LSU burst after barrier) ----
        {
            uint32_t af[4][4], bf[4][2];
#pragma unroll
            for (int mi = 0; mi < 4; ++mi) {
                uint32_t ra = (uint32_t)((wm * 64 + mi * 16) * 64) + arow + acol0;
                ldsm4(af[mi][0], af[mi][1], af[mi][2], af[mi][3], aS + ra);
            }
#pragma unroll
            for (int nj = 0; nj < 2; ++nj) {
                uint32_t rb = (uint32_t)((wn * 32 + nj * 16) * 64) + brow + bcol0;
                uint32_t t0, t1, t2, t3;
                ldsm4(t0, t1, t2, t3, bS + rb);
                bf[nj * 2][0] = t0; bf[nj * 2][1] = t1;
                bf[nj * 2 + 1][0] = t2; bf[nj * 2 + 1][1] = t3;
            }
#pragma unroll
            for (int mi = 0; mi < 4; ++mi)
#pragma unroll
                for (int ni = 0; ni < 4; ++ni)
                    mma_f16(acc[mi][ni], af[mi], bf[ni]);
        }

        // ---- prefetch kt+5 into stage stP (slot into kk=0's MMA shadow) ----
        if (kt + 5 < nk) {
            const uint32_t base = sb + stP * STAGE1;
            const size_t kb = (size_t)(kt + 5) * 64;
            size_t g0 = (size_t)cr * K2 + kb + (size_t)cc * 16;
            size_t g1 = (size_t)(cr + 64) * K2 + kb + (size_t)cc * 16;
            cpa16(base + off0,        pA + g0);
            cpa16(base + off1,        pA + g1);
            cpa16(base + ASEC + off0, pB + g0);
            cpa16(base + ASEC + off1, pB + g1);
        }
        asm volatile("cp.async.commit_group;" ::: "memory");

        // ---- kk = 1 ----
        {
            uint32_t af[4][4], bf[4][2];
#pragma unroll
            for (int mi = 0; mi < 4; ++mi) {
                uint32_t ra = (uint32_t)((wm * 64 + mi * 16) * 64) + arow + acol1;
                ldsm4(af[mi][0], af[mi][1], af[mi][2], af[mi][3], aS + ra);
            }
#pragma unroll
            for (int nj = 0; nj < 2; ++nj) {
                uint32_t rb = (uint32_t)((wn * 32 + nj * 16) * 64) + brow + bcol1;
                uint32_t t0, t1, t2, t3;
                ldsm4(t0, t1, t2, t3, bS + rb);
                bf[nj * 2][0] = t0; bf[nj * 2][1] = t1;
                bf[nj * 2 + 1][0] = t2; bf[nj * 2 + 1][1] = t3;
            }
#pragma unroll
            for (int mi = 0; mi < 4; ++mi)
#pragma unroll
                for (int ni = 0; ni < 4; ++ni)
                    mma_f16(acc[mi][ni], af[mi], bf[ni]);
        }

        if (++stC == NST1) stC = 0;
        if (++stP == NST1) stP = 0;
    }

    // ---- epilogue ----
    const size_t mw = m0 + wm * 64;
    const size_t nw = n0 + wn * 32;
    const int tr = lane >> 2;
    const int tc = (lane & 3) * 2;
#pragma unroll
    for (int mi = 0; mi < 4; ++mi)
#pragma unroll
        for (int nj = 0; nj < 4; ++nj) {
            const float* c = acc[mi][nj];
            const size_t row = mw + mi * 16 + tr;
            const size_t col = nw + nj * 8 + tc;
#pragma unroll
            for (int h = 0; h < 2; ++h) {
                const size_t base = (row + h * 8) * (size_t)N + col;
                float v0 = c[h * 2], v1 = c[h * 2 + 1];
                if (epi == 0) {                 // relu^2 -> fp16
                    v0 = fmaxf(v0, 0.0f); v0 *= v0;
                    v1 = fmaxf(v1, 0.0f); v1 *= v1;
                    *reinterpret_cast<uint32_t*>(Chf + base) =
                        ph2(__float2half_rn(v0), __float2half_rn(v1));
                } else if (epi == 1) {          // sigmoid -> fp32
                    float2 o;
                    o.x = 1.0f / (1.0f + expf(-v0));
                    o.y = 1.0f / (1.0f + expf(-v1));
                    *reinterpret_cast<float2*>(Cf + base) = o;
                } else {                        // * r -> fp32
                    float2 rv = *reinterpret_cast<const float2*>(Rm + base);
                    float2 o;
                    o.x = v0 * rv.x;
                    o.y = v1 * rv.y;
                    *reinterpret_cast<float2*>(Cf + base) = o;
                }
            }
        }
}

// ---------------- launch -----------------------------------------------------
extern "C" void kernel_launch(void* const* d_in, const int* in_sizes, int n_in,
                              void* d_out, int out_size) {
    const float* x  = (const float*)d_in[0];
    const float* ls = (const float*)d_in[1];
    const float* mk = (const float*)d_in[2];
    const float* mr = (const float*)d_in[3];
    const float* kw = (const float*)d_in[4];   // (F, C)
    const float* rw = (const float*)d_in[5];   // (C, C)
    const float* vw = (const float*)d_in[6];   // (C, F)
    float* out = (float*)d_out;

    __half *xk, *xr, *s, *kwp, *rwp, *vwp;
    float* r;
    cudaGetSymbolAddress((void**)&xk,  g_xk);
    cudaGetSymbolAddress((void**)&xr,  g_xr);
    cudaGetSymbolAddress((void**)&s,   g_s);
    cudaGetSymbolAddress((void**)&kwp, g_kw);
    cudaGetSymbolAddress((void**)&rwp, g_rw);
    cudaGetSymbolAddress((void**)&vwp, g_vw);
    cudaGetSymbolAddress((void**)&r,   g_r);

    cudaFuncSetAttribute(gemm_f16, cudaFuncAttributeMaxDynamicSharedMemorySize, SMEM1);

    // 1) token-shift mix -> fp16 xk, xr  (+ fused new_state copy)
    mix_kernel<<<(MDIM * (CDIM / 4)) / 256, 256>>>(
        (const float4*)x, (const float4*)ls, (const float4*)mk, (const float4*)mr,
        (uint2*)xk, (uint2*)xr, (float4*)(out + (size_t)MDIM * CDIM));

    // 2) weight prep: all single fp16
    {
        size_t n8;
        n8 = (size_t)FDIM * CDIM / 8;
        cvt_kernel<<<(unsigned)((n8 + 255) / 256), 256>>>((const float4*)kw, (uint4*)kwp, n8);
        n8 = (size_t)CDIM * CDIM / 8;
        cvt_kernel<<<(unsigned)((n8 + 255) / 256), 256>>>((const float4*)rw, (uint4*)rwp, n8);
        n8 = (size_t)CDIM * FDIM / 8;
        cvt_kernel<<<(unsigned)((n8 + 255) / 256), 256>>>((const float4*)vw, (uint4*)vwp, n8);
    }

    // 3) S = relu(xk @ Kw^T)^2 -> fp16           [M=8192, N=14336, K=4096]
    gemm_f16<<<(MDIM / 128) * (FDIM / 128), 256, SMEM1>>>(
        xk, kwp, FDIM, CDIM, FDIM / 128, 0, nullptr, s, nullptr);

    // 4) R = sigmoid(xr @ Rw^T) -> fp32          [M=8192, N=4096, K=4096]
    gemm_f16<<<(MDIM / 128) * (CDIM / 128), 256, SMEM1>>>(
        xr, rwp, CDIM, CDIM, CDIM / 128, 1, r, nullptr, nullptr);

    // 5) out = R * (S @ Vw^T)  -> fp32           [M=8192, N=4096, K=14336]
    gemm_f16<<<(MDIM / 128) * (CDIM / 128), 256, SMEM1>>>(
        s, vwp, CDIM, FDIM, CDIM / 128, 2, out, nullptr, r);
}

// round 16
// speedup vs baseline: 1.3419x; 1.0713x over previous
#include <cuda_runtime.h>
#include <cuda_fp16.h>
#include <cstdint>
#include <math.h>

#define BDIM 4
#define TDIM 2048
#define CDIM 4096
#define FDIM 14336
#define MDIM (BDIM * TDIM)   // 8192

// ---------------- scratch (device globals; allocation-free rule) -----------
__device__ __half g_xk [(size_t)MDIM * CDIM];
__device__ __half g_xr [(size_t)MDIM * CDIM];
__device__ __half g_s  [(size_t)MDIM * FDIM];
__device__ __half g_kw [(size_t)FDIM * CDIM];
__device__ __half g_rw [(size_t)CDIM * CDIM];
__device__ __half g_vw [(size_t)CDIM * FDIM];
__device__ float  g_r  [(size_t)MDIM * CDIM];

// ---------------- helpers ----------------------------------------------------
__device__ __forceinline__ uint32_t smem_u32(const void* p) {
    uint32_t a;
    asm("{ .reg .u64 t; cvta.to.shared.u64 t, %1; cvt.u32.u64 %0, t; }" : "=r"(a) : "l"(p));
    return a;
}
__device__ __forceinline__ void cpa16(uint32_t dst, const void* src) {
    asm volatile("cp.async.cg.shared.global [%0], [%1], 16;" :: "r"(dst), "l"(src));
}
__device__ __forceinline__ void ldsm4(uint32_t& r0, uint32_t& r1, uint32_t& r2, uint32_t& r3,
                                      uint32_t addr) {
    asm volatile("ldmatrix.sync.aligned.m8n8.x4.shared.b16 {%0,%1,%2,%3}, [%4];"
                 : "=r"(r0), "=r"(r1), "=r"(r2), "=r"(r3) : "r"(addr));
}
__device__ __forceinline__ void mma_f16(float* c, const uint32_t* a, const uint32_t* b) {
    asm volatile(
        "mma.sync.aligned.m16n8k16.row.col.f32.f16.f16.f32 "
        "{%0,%1,%2,%3}, {%4,%5,%6,%7}, {%8,%9}, {%0,%1,%2,%3};"
        : "+f"(c[0]), "+f"(c[1]), "+f"(c[2]), "+f"(c[3])
        : "r"(a[0]), "r"(a[1]), "r"(a[2]), "r"(a[3]), "r"(b[0]), "r"(b[1]));
}
__device__ __forceinline__ uint32_t ph2(__half a, __half b) {
    __half2 t = __halves2half2(a, b);
    return *reinterpret_cast<uint32_t*>(&t);
}

// 64B-row XOR swizzle: 16B chunk c at row r stored at chunk (c ^ ((r>>1)&3))
__device__ __forceinline__ uint32_t swoff(int r, int c) {
    return (uint32_t)(r * 64 + ((c ^ ((r >> 1) & 3)) << 4));
}

// ---------------- elementwise kernels ---------------------------------------
// mix + state fused: t==T-1 rows also write new_state
__global__ void mix_kernel(const float4* __restrict__ x,
                           const float4* __restrict__ ls,
                           const float4* __restrict__ mk,
                           const float4* __restrict__ mr,
                           uint2* __restrict__ xk, uint2* __restrict__ xr,
                           float4* __restrict__ outs) {
    const int C4 = CDIM / 4;
    int idx = blockIdx.x * blockDim.x + threadIdx.x;
    int c4 = idx % C4;
    int bt = idx / C4;
    int t  = bt % TDIM;
    int b  = bt / TDIM;

    float4 xv = x[idx];
    float4 pv = (t == 0) ? ls[b * C4 + c4] : x[idx - C4];
    float4 k4 = mk[c4];
    float4 r4 = mr[c4];

    float kk[4], rr[4];
    kk[0] = fmaf(pv.x - xv.x, k4.x, xv.x);
    kk[1] = fmaf(pv.y - xv.y, k4.y, xv.y);
    kk[2] = fmaf(pv.z - xv.z, k4.z, xv.z);
    kk[3] = fmaf(pv.w - xv.w, k4.w, xv.w);
    rr[0] = fmaf(pv.x - xv.x, r4.x, xv.x);
    rr[1] = fmaf(pv.y - xv.y, r4.y, xv.y);
    rr[2] = fmaf(pv.z - xv.z, r4.z, xv.z);
    rr[3] = fmaf(pv.w - xv.w, r4.w, xv.w);

    xk[idx] = make_uint2(ph2(__float2half_rn(kk[0]), __float2half_rn(kk[1])),
                         ph2(__float2half_rn(kk[2]), __float2half_rn(kk[3])));
    xr[idx] = make_uint2(ph2(__float2half_rn(rr[0]), __float2half_rn(rr[1])),
                         ph2(__float2half_rn(rr[2]), __float2half_rn(rr[3])));

    if (t == TDIM - 1)
        outs[b * C4 + c4] = xv;
}

// fused fp32->fp16 convert of all three weight matrices in one launch
#define KW8 ((size_t)FDIM * CDIM / 8)
#define RW8 ((size_t)CDIM * CDIM / 8)
#define VW8 ((size_t)CDIM * FDIM / 8)

__global__ void cvt3_kernel(const float4* __restrict__ kw, uint4* __restrict__ kwp,
                            const float4* __restrict__ rw, uint4* __restrict__ rwp,
                            const float4* __restrict__ vw, uint4* __restrict__ vwp) {
    size_t i = (size_t)blockIdx.x * blockDim.x + threadIdx.x;
    const float4* in;
    uint4* oh;
    if (i < KW8) {
        in = kw; oh = kwp;
    } else if (i < KW8 + RW8) {
        i -= KW8; in = rw; oh = rwp;
    } else {
        i -= KW8 + RW8;
        if (i >= VW8) return;
        in = vw; oh = vwp;
    }
    float4 a = in[2 * i], b = in[2 * i + 1];
    oh[i] = make_uint4(ph2(__float2half_rn(a.x), __float2half_rn(a.y)),
                       ph2(__float2half_rn(a.z), __float2half_rn(a.w)),
                       ph2(__float2half_rn(b.x), __float2half_rn(b.y)),
                       ph2(__float2half_rn(b.z), __float2half_rn(b.w)));
}

// ---------------- fp16 HMMA GEMM (all three GEMMs) ---------------------------
// C[M,N] = A[M,K] * B[N,K]^T, fp16 inputs, fp32 accum.
// CTA 128x128, 8 warps (256 thr), warp 64x32 (2x4), BK=32, 6-stage cp.async
// (wait_group 4), XOR-swizzled 64B rows, 2 CTAs/SM.
// Prefetch split 2+2 across the two kk MMA shadows; commit at iteration end.
// epi 0: relu^2->fp16 | 1: sigmoid->fp32 | 2: *Rm->fp32
#define ASEC   (128 * 64)            // 8192
#define BSEC   (128 * 64)            // 8192
#define STAGE1 (ASEC + BSEC)         // 16384
#define NST1   6
#define SMEM1  (NST1 * STAGE1)       // 98304

__global__ void __launch_bounds__(256, 2)
gemm_f16(const __half* __restrict__ A, const __half* __restrict__ B,
         int N, int K, int Ntiles, int epi,
         float* __restrict__ Cf, __half* __restrict__ Chf,
         const float* __restrict__ Rm) {
    extern __shared__ char smem[];
    const uint32_t sb = smem_u32(smem);
    const int tid  = threadIdx.x;
    const int wid  = tid >> 5;
    const int lane = tid & 31;
    const int wm   = wid & 1;        // 2 warp-rows (64 each)
    const int wn   = wid >> 1;       // 4 warp-cols (32 each)

    // band-swizzled tile mapping (bands of 16 M-tiles)
    int bid = blockIdx.x;
    int bandCtas = 16 * Ntiles;
    int band = bid / bandCtas, rmd = bid % bandCtas;
    int nt = rmd >> 4;
    int mt = band * 16 + (rmd & 15);
    const size_t m0 = (size_t)mt * 128;
    const size_t n0 = (size_t)nt * 128;

    const size_t K2 = (size_t)K * 2;
    const char* pA = (const char*)(A + m0 * (size_t)K);
    const char* pB = (const char*)(B + n0 * (size_t)K);

    const int nk = K >> 5;   // BK = 32

    const int cr = tid >> 2;          // row 0..63
    const int cc = tid & 3;           // 16B chunk in row
    const uint32_t off0 = swoff(cr, cc);
    const uint32_t off1 = swoff(cr + 64, cc);

    // prologue: stages 0..4
#pragma unroll
    for (int s = 0; s < 5; ++s) {
        const uint32_t base = sb + s * STAGE1;
        const size_t kb = (size_t)s * 64;
        size_t g0 = (size_t)cr * K2 + kb + (size_t)cc * 16;
        size_t g1 = (size_t)(cr + 64) * K2 + kb + (size_t)cc * 16;
        cpa16(base + off0,        pA + g0);
        cpa16(base + off1,        pA + g1);
        cpa16(base + ASEC + off0, pB + g0);
        cpa16(base + ASEC + off1, pB + g1);
        asm volatile("cp.async.commit_group;" ::: "memory");
    }

    float acc[4][4][4];
#pragma unroll
    for (int i = 0; i < 4; ++i)
#pragma unroll
        for (int j = 0; j < 4; ++j)
#pragma unroll
            for (int q = 0; q < 4; ++q) acc[i][j][q] = 0.0f;

    const int rl_a   = (lane & 7) + ((lane >> 3) & 1) * 8;
    const int sel_a  = (rl_a >> 1) & 3;
    const int cb_a   = lane >> 4;
    const uint32_t arow  = (uint32_t)(rl_a * 64);
    const uint32_t acol0 = (uint32_t)(((0 + cb_a) ^ sel_a) << 4);
    const uint32_t acol1 = (uint32_t)(((2 + cb_a) ^ sel_a) << 4);

    const int rl_b   = (lane & 7) + (lane >> 4) * 8;
    const int sel_b  = (rl_b >> 1) & 3;
    const int cb_b   = (lane >> 3) & 1;
    const uint32_t brow  = (uint32_t)(rl_b * 64);
    const uint32_t bcol0 = (uint32_t)(((0 + cb_b) ^ sel_b) << 4);
    const uint32_t bcol1 = (uint32_t)(((2 + cb_b) ^ sel_b) << 4);

    int stC = 0, stP = 5;
    for (int kt = 0; kt < nk; ++kt) {
        asm volatile("cp.async.wait_group 4;" ::: "memory");
        __syncthreads();

        const uint32_t sbase = sb + stC * STAGE1;
        const uint32_t aS = sbase;
        const uint32_t bS = sbase + ASEC;
        const bool doPf = (kt + 5 < nk);
        const uint32_t pbase = sb + stP * STAGE1;
        const size_t pkb = (size_t)(kt + 5) * 64;
        const size_t pg0 = (size_t)cr * K2 + pkb + (size_t)cc * 16;
        const size_t pg1 = (size_t)(cr + 64) * K2 + pkb + (size_t)cc * 16;

        // ---- kk = 0 ----
        {
            uint32_t af[4][4], bf[4][2];
#pragma unroll
            for (int mi = 0; mi < 4; ++mi) {
                uint32_t ra = (uint32_t)((wm * 64 + mi * 16) * 64) + arow + acol0;
                ldsm4(af[mi][0], af[mi][1], af[mi][2], af[mi][3], aS + ra);
            }
#pragma unroll
            for (int nj = 0; nj < 2; ++nj) {
                uint32_t rb = (uint32_t)((wn * 32 + nj * 16) * 64) + brow + bcol0;
                uint32_t t0, t1, t2, t3;
                ldsm4(t0, t1, t2, t3, bS + rb);
                bf[nj * 2][0] = t0; bf[nj * 2][1] = t1;
                bf[nj * 2 + 1][0] = t2; bf[nj * 2 + 1][1] = t3;
            }
#pragma unroll
            for (int mi = 0; mi < 4; ++mi)
#pragma unroll
                for (int ni = 0; ni < 4; ++ni)
                    mma_f16(acc[mi][ni], af[mi], bf[ni]);
        }

        // prefetch A halves in kk=0's MMA shadow
        if (doPf) {
            cpa16(pbase + off0, pA + pg0);
            cpa16(pbase + off1, pA + pg1);
        }

        // ---- kk = 1 ----
        {
            uint32_t af[4][4], bf[4][2];
#pragma unroll
            for (int mi = 0; mi < 4; ++mi) {
                uint32_t ra = (uint32_t)((wm * 64 + mi * 16) * 64) + arow + acol1;
                ldsm4(af[mi][0], af[mi][1], af[mi][2], af[mi][3], aS + ra);
            }
#pragma unroll
            for (int nj = 0; nj < 2; ++nj) {
                uint32_t rb = (uint32_t)((wn * 32 + nj * 16) * 64) + brow + bcol1;
                uint32_t t0, t1, t2, t3;
                ldsm4(t0, t1, t2, t3, bS + rb);
                bf[nj * 2][0] = t0; bf[nj * 2][1] = t1;
                bf[nj * 2 + 1][0] = t2; bf[nj * 2 + 1][1] = t3;
            }
#pragma unroll
            for (int mi = 0; mi < 4; ++mi)
#pragma unroll
                for (int ni = 0; ni < 4; ++ni)
                    mma_f16(acc[mi][ni], af[mi], bf[ni]);
        }

        // prefetch B halves in kk=1's MMA shadow, then commit
        if (doPf) {
            cpa16(pbase + ASEC + off0, pB + pg0);
            cpa16(pbase + ASEC + off1, pB + pg1);
        }
        asm volatile("cp.async.commit_group;" ::: "memory");

        if (++stC == NST1) stC = 0;
        if (++stP == NST1) stP = 0;
    }

    // ---- epilogue ----
    const size_t mw = m0 + wm * 64;
    const size_t nw = n0 + wn * 32;
    const int tr = lane >> 2;
    const int tc = (lane & 3) * 2;
#pragma unroll
    for (int mi = 0; mi < 4; ++mi)
#pragma unroll
        for (int nj = 0; nj < 4; ++nj) {
            const float* c = acc[mi][nj];
            const size_t row = mw + mi * 16 + tr;
            const size_t col = nw + nj * 8 + tc;
#pragma unroll
            for (int h = 0; h < 2; ++h) {
                const size_t base = (row + h * 8) * (size_t)N + col;
                float v0 = c[h * 2], v1 = c[h * 2 + 1];
                if (epi == 0) {                 // relu^2 -> fp16
                    v0 = fmaxf(v0, 0.0f); v0 *= v0;
                    v1 = fmaxf(v1, 0.0f); v1 *= v1;
                    *reinterpret_cast<uint32_t*>(Chf + base) =
                        ph2(__float2half_rn(v0), __float2half_rn(v1));
                } else if (epi == 1) {          // sigmoid -> fp32
                    float2 o;
                    o.x = 1.0f / (1.0f + expf(-v0));
                    o.y = 1.0f / (1.0f + expf(-v1));
                    *reinterpret_cast<float2*>(Cf + base) = o;
                } else {                        // * r -> fp32
                    float2 rv = *reinterpret_cast<const float2*>(Rm + base);
                    float2 o;
                    o.x = v0 * rv.x;
                    o.y = v1 * rv.y;
                    *reinterpret_cast<float2*>(Cf + base) = o;
                }
            }
        }
}

// ---------------- launch -----------------------------------------------------
extern "C" void kernel_launch(void* const* d_in, const int* in_sizes, int n_in,
                              void* d_out, int out_size) {
    const float* x  = (const float*)d_in[0];
    const float* ls = (const float*)d_in[1];
    const float* mk = (const float*)d_in[2];
    const float* mr = (const float*)d_in[3];
    const float* kw = (const float*)d_in[4];   // (F, C)
    const float* rw = (const float*)d_in[5];   // (C, C)
    const float* vw = (const float*)d_in[6];   // (C, F)
    float* out = (float*)d_out;

    __half *xk, *xr, *s, *kwp, *rwp, *vwp;
    float* r;
    cudaGetSymbolAddress((void**)&xk,  g_xk);
    cudaGetSymbolAddress((void**)&xr,  g_xr);
    cudaGetSymbolAddress((void**)&s,   g_s);
    cudaGetSymbolAddress((void**)&kwp, g_kw);
    cudaGetSymbolAddress((void**)&rwp, g_rw);
    cudaGetSymbolAddress((void**)&vwp, g_vw);
    cudaGetSymbolAddress((void**)&r,   g_r);

    cudaFuncSetAttribute(gemm_f16, cudaFuncAttributeMaxDynamicSharedMemorySize, SMEM1);

    // 1) token-shift mix -> fp16 xk, xr  (+ fused new_state copy)
    mix_kernel<<<(MDIM * (CDIM / 4)) / 256, 256>>>(
        (const float4*)x, (const float4*)ls, (const float4*)mk, (const float4*)mr,
        (uint2*)xk, (uint2*)xr, (float4*)(out + (size_t)MDIM * CDIM));

    // 2) weight prep: all three converts in one launch
    {
        size_t total = KW8 + RW8 + VW8;
        cvt3_kernel<<<(unsigned)((total + 255) / 256), 256>>>(
            (const float4*)kw, (uint4*)kwp,
            (const float4*)rw, (uint4*)rwp,
            (const float4*)vw, (uint4*)vwp);
    }

    // 3) S = relu(xk @ Kw^T)^2 -> fp16           [M=8192, N=14336, K=4096]
    gemm_f16<<<(MDIM / 128) * (FDIM / 128), 256, SMEM1>>>(
        xk, kwp, FDIM, CDIM, FDIM / 128, 0, nullptr, s, nullptr);

    // 4) R = sigmoid(xr @ Rw^T) -> fp32          [M=8192, N=4096, K=4096]
    gemm_f16<<<(MDIM / 128) * (CDIM / 128), 256, SMEM1>>>(
        xr, rwp, CDIM, CDIM, CDIM / 128, 1, r, nullptr, nullptr);

    // 5) out = R * (S @ Vw^T)  -> fp32           [M=8192, N=4096, K=14336]
    gemm_f16<<<(MDIM / 128) * (CDIM / 128), 256, SMEM1>>>(
        s, vwp, CDIM, FDIM, CDIM / 128, 2, out, nullptr, r);
}